// round 5
// baseline (speedup 1.0000x reference)
#include <cuda_runtime.h>
#include <cuda_bf16.h>

#define LL 512
#define DD 512
#define HH 512

typedef unsigned long long ull;

// ---------------- device scratch ----------------
__device__ float g_u[LL * DD];
__device__ float g_w[LL * DD];
__device__ float g_e[LL * LL];
__device__ float g_a[LL * LL];
__device__ float g_c[LL * DD];
__device__ float g_gi_f[LL * 3 * HH];
__device__ float g_gi_b[LL * 3 * HH];
// tagged h state: [dir][slot][h] -> (value bits, tag). 8B aligned => atomic pair.
__device__ uint2 g_ht[2][2][HH];

__device__ __forceinline__ float sigm_(float x) {
    return __fdividef(1.f, 1.f + __expf(-x));
}
__device__ __forceinline__ float tanh_(float x) {
    return 1.f - __fdividef(2.f, __expf(x + x) + 1.f);
}
__device__ __forceinline__ void ffma2(ull& d, ull a, ull b) {
    asm("fma.rn.f32x2 %0, %1, %2, %0;" : "+l"(d) : "l"(a), "l"(b));
}
__device__ __forceinline__ ull packff(float x) {
    ull r; asm("mov.b64 %0, {%1, %1};" : "=l"(r) : "f"(x)); return r;
}
__device__ __forceinline__ float2 unpk(ull v) {
    float2 f; asm("mov.b64 {%0, %1}, %2;" : "=f"(f.x), "=f"(f.y) : "l"(v)); return f;
}

// ---------------- init (zero tagged h state) ----------------
__global__ void init_zero() {
    int i = blockIdx.x * 1024 + threadIdx.x;
    if (i < 4096) ((unsigned int*)g_ht)[i] = 0u;
}

// ---------------- GEMM core (f32x2 packed) ----------------
// C[M,N] = concat(A0[:,0:K0], A1[:,0:K-K0]) * op(B) + bias
// transB=1: B is [N,K] row-major. transB=0: B is [K,N].
__device__ __forceinline__ void gemm_core(
    const float* __restrict__ A0, const float* __restrict__ A1, int K0,
    const float* __restrict__ B, const float* __restrict__ bias,
    float* __restrict__ C, int N, int K, int transB)
{
    __shared__ __align__(16) float As[16][68];
    __shared__ __align__(16) float Bs[16][68];
    const int tid = threadIdx.x;
    const int m0 = blockIdx.y * 64, n0 = blockIdx.x * 64;
    const int tm = (tid >> 4) * 4, tn = (tid & 15) * 4;
    const int K1 = K - K0;
    ull acc[4][2] = {};
    for (int k0 = 0; k0 < K; k0 += 16) {
#pragma unroll
        for (int i = 0; i < 4; i++) {
            int e = tid + 256 * i;
            {
                int kk = e & 15, row = e >> 4, gk = k0 + kk;
                As[kk][row] = (gk < K0) ? A0[(m0 + row) * K0 + gk]
                                        : A1[(m0 + row) * K1 + gk - K0];
            }
            if (transB) {
                int kk = e & 15, row = e >> 4;
                Bs[kk][row] = B[(size_t)(n0 + row) * K + k0 + kk];
            } else {
                int n = e & 63, kk = e >> 6;
                Bs[kk][n] = B[(size_t)(k0 + kk) * N + n0 + n];
            }
        }
        __syncthreads();
#pragma unroll
        for (int kk = 0; kk < 16; kk++) {
            float4 a = *(const float4*)&As[kk][tm];
            const ull* bp = (const ull*)&Bs[kk][tn];
            ull b01 = bp[0], b23 = bp[1];
            ull a0 = packff(a.x), a1 = packff(a.y), a2 = packff(a.z), a3 = packff(a.w);
            ffma2(acc[0][0], a0, b01); ffma2(acc[0][1], a0, b23);
            ffma2(acc[1][0], a1, b01); ffma2(acc[1][1], a1, b23);
            ffma2(acc[2][0], a2, b01); ffma2(acc[2][1], a2, b23);
            ffma2(acc[3][0], a3, b01); ffma2(acc[3][1], a3, b23);
        }
        __syncthreads();
    }
#pragma unroll
    for (int i = 0; i < 4; i++) {
        float2 c01 = unpk(acc[i][0]), c23 = unpk(acc[i][1]);
        float* cp = C + (size_t)(m0 + tm + i) * N + n0 + tn;
        float b0 = 0.f, b1 = 0.f, b2 = 0.f, b3 = 0.f;
        if (bias) { b0 = bias[n0+tn]; b1 = bias[n0+tn+1]; b2 = bias[n0+tn+2]; b3 = bias[n0+tn+3]; }
        cp[0] = c01.x + b0; cp[1] = c01.y + b1; cp[2] = c23.x + b2; cp[3] = c23.y + b3;
    }
}

__global__ void gemm_uw(const float* __restrict__ v,
                        const float* __restrict__ w1, const float* __restrict__ b1,
                        const float* __restrict__ w2, const float* __restrict__ b2) {
    if (blockIdx.z == 0) gemm_core(v, v, 512, w1, b1, g_u, 512, 512, 1);
    else                 gemm_core(v, v, 512, w2, b2, g_w, 512, 512, 1);
}
__global__ void gemm_c(const float* __restrict__ v) {
    gemm_core(g_a, g_a, 512, v, nullptr, g_c, 512, 512, 0);
}
__global__ void gemm_gi(const float* __restrict__ v,
                        const float* __restrict__ wf, const float* __restrict__ bf,
                        const float* __restrict__ wb, const float* __restrict__ bb) {
    if (blockIdx.z == 0) gemm_core(v, g_c, 512, wf, bf, g_gi_f, 1536, 1024, 1);
    else                 gemm_core(v, g_c, 512, wb, bb, g_gi_b, 1536, 1024, 1);
}

// ---------------- e[t,j] = sum_d tanh(u[j,d]+w[t,d]) * v[j,d] ----------------
__global__ void attn_e(const float* __restrict__ v) {
    __shared__ float us[32][33], vs[32][33], ws[16][33];
    const int tx = threadIdx.x, ty = threadIdx.y;   // tx: local j, ty: local t
    const int j0 = blockIdx.x * 32, t0 = blockIdx.y * 16;
    float acc = 0.f;
    for (int d0 = 0; d0 < DD; d0 += 32) {
        us[ty][tx]      = g_u[(j0 + ty) * DD + d0 + tx];
        us[ty + 16][tx] = g_u[(j0 + ty + 16) * DD + d0 + tx];
        vs[ty][tx]      = v[(j0 + ty) * DD + d0 + tx];
        vs[ty + 16][tx] = v[(j0 + ty + 16) * DD + d0 + tx];
        ws[ty][tx]      = g_w[(t0 + ty) * DD + d0 + tx];
        __syncthreads();
#pragma unroll
        for (int dd = 0; dd < 32; dd++) {
            float x = us[tx][dd] + ws[ty][dd];
            float th = 1.f - __fdividef(2.f, __expf(x + x) + 1.f);
            acc = fmaf(th, vs[tx][dd], acc);
        }
        __syncthreads();
    }
    g_e[(t0 + ty) * LL + j0 + tx] = acc;
}

// ---------------- softmax rows ----------------
__global__ void softmax_rows() {
    __shared__ float red[16];
    __shared__ float bval;
    const int t = blockIdx.x, tid = threadIdx.x, w = tid >> 5, l = tid & 31;
    float x = g_e[t * LL + tid];
    float m = x;
#pragma unroll
    for (int o = 16; o; o >>= 1) m = fmaxf(m, __shfl_xor_sync(~0u, m, o));
    if (l == 0) red[w] = m;
    __syncthreads();
    if (tid == 0) {
        float mm = red[0];
#pragma unroll
        for (int i = 1; i < 16; i++) mm = fmaxf(mm, red[i]);
        bval = mm;
    }
    __syncthreads();
    float p = __expf(x - bval);
    float s = p;
#pragma unroll
    for (int o = 16; o; o >>= 1) s += __shfl_xor_sync(~0u, s, o);
    if (l == 0) red[w] = s;
    __syncthreads();
    if (tid == 0) {
        float ss = red[0];
#pragma unroll
        for (int i = 1; i < 16; i++) ss += red[i];
        bval = ss;
    }
    __syncthreads();
    g_a[t * LL + tid] = __fdividef(p, bval);
}

// ---------------- bidirectional GRU scan: tagged-value dataflow ----------------
// 64 CTAs: dir = bid>>5, 32 CTAs per dir, warp <-> one h index (16 warps/CTA).
// No barriers in the step loop: each warp polls (value,tag) pairs directly.
__global__ void __launch_bounds__(512, 1) gru_scan(
    const float* __restrict__ whh_f, const float* __restrict__ bhh_f,
    const float* __restrict__ whh_b, const float* __restrict__ bhh_b,
    float* __restrict__ out)
{
    const int dir = blockIdx.x >> 5, cta = blockIdx.x & 31;
    const int wrp = threadIdx.x >> 5, lane = threadIdx.x & 31;
    const int j = cta * 16 + wrp;  // this warp's h index
    const float* whh = dir ? whh_b : whh_f;
    const float* bhh = dir ? bhh_b : bhh_f;
    const float* gi  = dir ? g_gi_b : g_gi_f;

    float wr[16], wz[16], wn[16];
#pragma unroll
    for (int i = 0; i < 16; i++) {
        int k = lane + 32 * i;
        wr[i] = whh[(size_t)j * HH + k];
        wz[i] = whh[(size_t)(HH + j) * HH + k];
        wn[i] = whh[(size_t)(2 * HH + j) * HH + k];
    }
    const float bhr = bhh[j], bhz = bhh[HH + j], bhn = bhh[2 * HH + j];
    const int jl = j & 31, ji = j >> 5;   // lane/index holding h[j]

    for (int s = 0; s < LL; s++) {
        const int t = dir ? (LL - 1 - s) : s;
        // gi loads (independent of h) issue before the poll
        float giR = 0.f, giZ = 0.f, giN = 0.f;
        if (lane == 0) {
            const float* gt = gi + (size_t)t * (3 * HH);
            giR = __ldg(&gt[j]); giZ = __ldg(&gt[HH + j]); giN = __ldg(&gt[2 * HH + j]);
        }
        // poll h_s: slot s&1, expect tag == s
        const uint2* hp = g_ht[dir][s & 1];
        float hv[16];
        unsigned need = 0xFFFFu;
        while (need) {
#pragma unroll
            for (int i = 0; i < 16; i++) {
                if (need & (1u << i)) {
                    unsigned b, tg;
                    asm volatile("ld.acquire.gpu.global.v2.b32 {%0,%1}, [%2];"
                                 : "=r"(b), "=r"(tg)
                                 : "l"(&hp[lane + 32 * i]) : "memory");
                    if (tg == (unsigned)s) { hv[i] = __uint_as_float(b); need &= ~(1u << i); }
                }
            }
        }
        float aR = 0.f, aZ = 0.f, aN = 0.f, hsel = 0.f;
#pragma unroll
        for (int i = 0; i < 16; i++) {
            aR = fmaf(wr[i], hv[i], aR);
            aZ = fmaf(wz[i], hv[i], aZ);
            aN = fmaf(wn[i], hv[i], aN);
            if (i == ji) hsel = hv[i];
        }
#pragma unroll
        for (int o = 16; o; o >>= 1) {
            aR += __shfl_xor_sync(0xffffffffu, aR, o);
            aZ += __shfl_xor_sync(0xffffffffu, aZ, o);
            aN += __shfl_xor_sync(0xffffffffu, aN, o);
        }
        float hprev = __shfl_sync(0xffffffffu, hsel, jl);
        if (lane == 0) {
            float r = sigm_(giR + aR + bhr);
            float z = sigm_(giZ + aZ + bhz);
            float n = tanh_(giN + r * (aN + bhn));
            float hnew = (1.f - z) * n + z * hprev;
            unsigned hb = __float_as_uint(hnew);
            asm volatile("st.release.gpu.global.v2.b32 [%0], {%1,%2};"
                         :: "l"(&g_ht[dir][(s + 1) & 1][j]), "r"(hb), "r"((unsigned)(s + 1))
                         : "memory");
            out[(size_t)t * (2 * HH) + dir * HH + j] = hnew;
        }
    }
}

// ---------------- launch ----------------
extern "C" void kernel_launch(void* const* d_in, const int* in_sizes, int n_in,
                              void* d_out, int out_size) {
    const float* v     = (const float*)d_in[0];
    const float* w1    = (const float*)d_in[1];
    const float* b1    = (const float*)d_in[2];
    const float* w2    = (const float*)d_in[3];
    const float* b2    = (const float*)d_in[4];
    const float* wih_f = (const float*)d_in[5];
    const float* whh_f = (const float*)d_in[6];
    const float* bih_f = (const float*)d_in[7];
    const float* bhh_f = (const float*)d_in[8];
    const float* wih_b = (const float*)d_in[9];
    const float* whh_b = (const float*)d_in[10];
    const float* bih_b = (const float*)d_in[11];
    const float* bhh_b = (const float*)d_in[12];
    float* out = (float*)d_out;

    init_zero<<<4, 1024>>>();
    gemm_uw<<<dim3(8, 8, 2), 256>>>(v, w1, b1, w2, b2);
    attn_e<<<dim3(16, 32), dim3(32, 16)>>>(v);
    softmax_rows<<<512, 512>>>();
    gemm_c<<<dim3(8, 8), 256>>>(v);
    gemm_gi<<<dim3(24, 8, 2), 256>>>(v, wih_f, bih_f, wih_b, bih_b);
    gru_scan<<<64, 512>>>(whh_f, bhh_f, whh_b, bhh_b, out);
}

// round 6
// speedup vs baseline: 2.8354x; 2.8354x over previous
#include <cuda_runtime.h>
#include <cuda_bf16.h>

#define LL 512
#define DD 512
#define HH 512

typedef unsigned long long ull;

// ---------------- device scratch ----------------
__device__ float g_u[LL * DD];
__device__ float g_w[LL * DD];
__device__ float g_e[LL * LL];
__device__ float g_a[LL * LL];
__device__ float g_c[LL * DD];
__device__ float g_gi_f[LL * 3 * HH];
__device__ float g_gi_b[LL * 3 * HH];
__device__ float g_h[2][2][HH];               // fallback: [dir][parity][h]
__device__ unsigned int g_flag[2][32][32];    // fallback: per-producer flag lines

__device__ __forceinline__ float sigm_(float x) {
    return __fdividef(1.f, 1.f + __expf(-x));
}
__device__ __forceinline__ float tanh_(float x) {
    return 1.f - __fdividef(2.f, __expf(x + x) + 1.f);
}
__device__ __forceinline__ unsigned int ld_acq(const unsigned int* p) {
    unsigned int v;
    asm volatile("ld.acquire.gpu.global.u32 %0, [%1];" : "=r"(v) : "l"(p) : "memory");
    return v;
}
__device__ __forceinline__ void st_rel(unsigned int* p, unsigned int v) {
    asm volatile("st.release.gpu.global.u32 [%0], %1;" :: "l"(p), "r"(v) : "memory");
}
__device__ __forceinline__ void ffma2(ull& d, ull a, ull b) {
    asm("fma.rn.f32x2 %0, %1, %2, %0;" : "+l"(d) : "l"(a), "l"(b));
}
__device__ __forceinline__ ull packff(float x) {
    ull r; asm("mov.b64 %0, {%1, %1};" : "=l"(r) : "f"(x)); return r;
}
__device__ __forceinline__ ull pack2(float x, float y) {
    ull r; asm("mov.b64 %0, {%1, %2};" : "=l"(r) : "f"(x), "f"(y)); return r;
}
__device__ __forceinline__ float2 unpk(ull v) {
    float2 f; asm("mov.b64 {%0, %1}, %2;" : "=f"(f.x), "=f"(f.y) : "l"(v)); return f;
}
__device__ __forceinline__ unsigned smem_u32(const void* p) {
    unsigned a;
    asm("{ .reg .u64 t; cvta.to.shared.u64 t, %1; cvt.u32.u64 %0, t; }" : "=r"(a) : "l"(p));
    return a;
}
__device__ __forceinline__ unsigned ctarank_() {
    unsigned r; asm("mov.u32 %0, %%cluster_ctarank;" : "=r"(r)); return r;
}

// ---------------- init (zero fallback h + flags) ----------------
__global__ void init_zero() {
    int i = blockIdx.x * 1024 + threadIdx.x;
    if (i < 2048) ((unsigned int*)g_flag)[i] = 0u;
    if (i < 2048) ((float*)g_h)[i] = 0.f;
}

// ---------------- GEMM core (f32x2 packed) ----------------
__device__ __forceinline__ void gemm_core(
    const float* __restrict__ A0, const float* __restrict__ A1, int K0,
    const float* __restrict__ B, const float* __restrict__ bias,
    float* __restrict__ C, int N, int K, int transB)
{
    __shared__ __align__(16) float As[16][68];
    __shared__ __align__(16) float Bs[16][68];
    const int tid = threadIdx.x;
    const int m0 = blockIdx.y * 64, n0 = blockIdx.x * 64;
    const int tm = (tid >> 4) * 4, tn = (tid & 15) * 4;
    const int K1 = K - K0;
    ull acc[4][2] = {};
    for (int k0 = 0; k0 < K; k0 += 16) {
#pragma unroll
        for (int i = 0; i < 4; i++) {
            int e = tid + 256 * i;
            {
                int kk = e & 15, row = e >> 4, gk = k0 + kk;
                As[kk][row] = (gk < K0) ? A0[(m0 + row) * K0 + gk]
                                        : A1[(m0 + row) * K1 + gk - K0];
            }
            if (transB) {
                int kk = e & 15, row = e >> 4;
                Bs[kk][row] = B[(size_t)(n0 + row) * K + k0 + kk];
            } else {
                int n = e & 63, kk = e >> 6;
                Bs[kk][n] = B[(size_t)(k0 + kk) * N + n0 + n];
            }
        }
        __syncthreads();
#pragma unroll
        for (int kk = 0; kk < 16; kk++) {
            float4 a = *(const float4*)&As[kk][tm];
            const ull* bp = (const ull*)&Bs[kk][tn];
            ull b01 = bp[0], b23 = bp[1];
            ull a0 = packff(a.x), a1 = packff(a.y), a2 = packff(a.z), a3 = packff(a.w);
            ffma2(acc[0][0], a0, b01); ffma2(acc[0][1], a0, b23);
            ffma2(acc[1][0], a1, b01); ffma2(acc[1][1], a1, b23);
            ffma2(acc[2][0], a2, b01); ffma2(acc[2][1], a2, b23);
            ffma2(acc[3][0], a3, b01); ffma2(acc[3][1], a3, b23);
        }
        __syncthreads();
    }
#pragma unroll
    for (int i = 0; i < 4; i++) {
        float2 c01 = unpk(acc[i][0]), c23 = unpk(acc[i][1]);
        float* cp = C + (size_t)(m0 + tm + i) * N + n0 + tn;
        float b0 = 0.f, b1 = 0.f, b2 = 0.f, b3 = 0.f;
        if (bias) { b0 = bias[n0+tn]; b1 = bias[n0+tn+1]; b2 = bias[n0+tn+2]; b3 = bias[n0+tn+3]; }
        cp[0] = c01.x + b0; cp[1] = c01.y + b1; cp[2] = c23.x + b2; cp[3] = c23.y + b3;
    }
}

__global__ void gemm_uw(const float* __restrict__ v,
                        const float* __restrict__ w1, const float* __restrict__ b1,
                        const float* __restrict__ w2, const float* __restrict__ b2) {
    if (blockIdx.z == 0) gemm_core(v, v, 512, w1, b1, g_u, 512, 512, 1);
    else                 gemm_core(v, v, 512, w2, b2, g_w, 512, 512, 1);
}
__global__ void gemm_c(const float* __restrict__ v) {
    gemm_core(g_a, g_a, 512, v, nullptr, g_c, 512, 512, 0);
}
__global__ void gemm_gi(const float* __restrict__ v,
                        const float* __restrict__ wf, const float* __restrict__ bf,
                        const float* __restrict__ wb, const float* __restrict__ bb) {
    if (blockIdx.z == 0) gemm_core(v, g_c, 512, wf, bf, g_gi_f, 1536, 1024, 1);
    else                 gemm_core(v, g_c, 512, wb, bb, g_gi_b, 1536, 1024, 1);
}

// ---------------- attn e ----------------
__global__ void attn_e(const float* __restrict__ v) {
    __shared__ float us[32][33], vs[32][33], ws[16][33];
    const int tx = threadIdx.x, ty = threadIdx.y;
    const int j0 = blockIdx.x * 32, t0 = blockIdx.y * 16;
    float acc = 0.f;
    for (int d0 = 0; d0 < DD; d0 += 32) {
        us[ty][tx]      = g_u[(j0 + ty) * DD + d0 + tx];
        us[ty + 16][tx] = g_u[(j0 + ty + 16) * DD + d0 + tx];
        vs[ty][tx]      = v[(j0 + ty) * DD + d0 + tx];
        vs[ty + 16][tx] = v[(j0 + ty + 16) * DD + d0 + tx];
        ws[ty][tx]      = g_w[(t0 + ty) * DD + d0 + tx];
        __syncthreads();
#pragma unroll
        for (int dd = 0; dd < 32; dd++) {
            float x = us[tx][dd] + ws[ty][dd];
            float th = 1.f - __fdividef(2.f, __expf(x + x) + 1.f);
            acc = fmaf(th, vs[tx][dd], acc);
        }
        __syncthreads();
    }
    g_e[(t0 + ty) * LL + j0 + tx] = acc;
}

// ---------------- softmax rows ----------------
__global__ void softmax_rows() {
    __shared__ float red[16];
    __shared__ float bval;
    const int t = blockIdx.x, tid = threadIdx.x, w = tid >> 5, l = tid & 31;
    float x = g_e[t * LL + tid];
    float m = x;
#pragma unroll
    for (int o = 16; o; o >>= 1) m = fmaxf(m, __shfl_xor_sync(~0u, m, o));
    if (l == 0) red[w] = m;
    __syncthreads();
    if (tid == 0) {
        float mm = red[0];
#pragma unroll
        for (int i = 1; i < 16; i++) mm = fmaxf(mm, red[i]);
        bval = mm;
    }
    __syncthreads();
    float p = __expf(x - bval);
    float s = p;
#pragma unroll
    for (int o = 16; o; o >>= 1) s += __shfl_xor_sync(~0u, s, o);
    if (l == 0) red[w] = s;
    __syncthreads();
    if (tid == 0) {
        float ss = red[0];
#pragma unroll
        for (int i = 1; i < 16; i++) ss += red[i];
        bval = ss;
    }
    __syncthreads();
    g_a[t * LL + tid] = __fdividef(p, bval);
}

// ================= GRU scan: 16-CTA cluster, DSMEM h exchange =================
// grid 32, cluster 16 -> 2 clusters (dir 0/1). 512 thr: warp owns h j0=rank*32+2w
// and j0+1. Weights interleaved-packed (w_j0[k], w_j1[k]) -> 48 f32x2 regs.
__global__ void __launch_bounds__(512, 1) gru_cluster(
    const float* __restrict__ whh_f, const float* __restrict__ bhh_f,
    const float* __restrict__ whh_b, const float* __restrict__ bhh_b,
    float* __restrict__ out)
{
    __shared__ __align__(16) float hbuf[2][HH];
    const int dir = blockIdx.x >> 4;
    const unsigned rank = ctarank_();
    const int wrp = threadIdx.x >> 5, lane = threadIdx.x & 31;
    const int j0 = (int)rank * 32 + wrp * 2;
    const int myj = j0 + (lane & 1);
    const float* whh = dir ? whh_b : whh_f;
    const float* bhh = dir ? bhh_b : bhh_f;
    const float* gi  = dir ? g_gi_b : g_gi_f;
    float* outp = out + dir * HH;

    ull wt[3][16];
#pragma unroll
    for (int g = 0; g < 3; g++) {
        const float* r0 = whh + ((size_t)(g * HH + j0)) * HH + lane * 16;
        const float* r1 = r0 + HH;
#pragma unroll
        for (int c = 0; c < 16; c++) wt[g][c] = pack2(r0[c], r1[c]);
    }
    const float bR = bhh[myj], bZ = bhh[HH + myj], bN = bhh[2 * HH + myj];

    for (int i = threadIdx.x; i < HH; i += 512) hbuf[0][i] = 0.f;
    const unsigned sb0 = smem_u32(&hbuf[0][0]);
    const unsigned sb1 = smem_u32(&hbuf[1][0]);
    __syncthreads();
    asm volatile("barrier.cluster.arrive.aligned;" ::: "memory");
    asm volatile("barrier.cluster.wait.aligned;" ::: "memory");

    for (int s = 0; s < LL; s++) {
        const int t = dir ? (LL - 1 - s) : s;
        float giR = 0.f, giZ = 0.f, giN = 0.f;
        if (lane < 2) {
            const float* gt = gi + (size_t)t * (3 * HH);
            giR = __ldg(gt + myj); giZ = __ldg(gt + HH + myj); giN = __ldg(gt + 2 * HH + myj);
        }
        const float* hp = hbuf[s & 1];
        ull aR = 0, aZ = 0, aN = 0;
#pragma unroll
        for (int c4 = 0; c4 < 4; c4++) {
            float4 hv = *(const float4*)(hp + lane * 16 + c4 * 4);
            ull h0 = packff(hv.x), h1 = packff(hv.y), h2 = packff(hv.z), h3 = packff(hv.w);
            ffma2(aR, wt[0][c4*4+0], h0); ffma2(aZ, wt[1][c4*4+0], h0); ffma2(aN, wt[2][c4*4+0], h0);
            ffma2(aR, wt[0][c4*4+1], h1); ffma2(aZ, wt[1][c4*4+1], h1); ffma2(aN, wt[2][c4*4+1], h1);
            ffma2(aR, wt[0][c4*4+2], h2); ffma2(aZ, wt[1][c4*4+2], h2); ffma2(aN, wt[2][c4*4+2], h2);
            ffma2(aR, wt[0][c4*4+3], h3); ffma2(aZ, wt[1][c4*4+3], h3); ffma2(aN, wt[2][c4*4+3], h3);
        }
        float2 fR = unpk(aR), fZ = unpk(aZ), fN = unpk(aN);
#pragma unroll
        for (int o = 16; o; o >>= 1) {
            fR.x += __shfl_xor_sync(~0u, fR.x, o);
            fR.y += __shfl_xor_sync(~0u, fR.y, o);
            fZ.x += __shfl_xor_sync(~0u, fZ.x, o);
            fZ.y += __shfl_xor_sync(~0u, fZ.y, o);
            fN.x += __shfl_xor_sync(~0u, fN.x, o);
            fN.y += __shfl_xor_sync(~0u, fN.y, o);
        }
        float hnew = 0.f;
        if (lane < 2) {
            float aRs = lane ? fR.y : fR.x;
            float aZs = lane ? fZ.y : fZ.x;
            float aNs = lane ? fN.y : fN.x;
            float rr = sigm_(giR + aRs + bR);
            float zz = sigm_(giZ + aZs + bZ);
            float nn = tanh_(giN + rr * (aNs + bN));
            float hprev = hp[myj];
            hnew = (1.f - zz) * nn + zz * hprev;
            outp[(size_t)t * (2 * HH) + myj] = hnew;
        }
        float hv2 = __shfl_sync(0xffffffffu, hnew, lane & 1);
        unsigned laddr = ((s + 1) & 1 ? sb1 : sb0) + (unsigned)myj * 4u;
        unsigned raddr;
        asm("mapa.shared::cluster.u32 %0, %1, %2;" : "=r"(raddr) : "r"(laddr), "r"(lane >> 1));
        asm volatile("st.shared::cluster.f32 [%0], %1;" :: "r"(raddr), "f"(hv2) : "memory");
        asm volatile("barrier.cluster.arrive.aligned;" ::: "memory");
        asm volatile("barrier.cluster.wait.aligned;" ::: "memory");
    }
}

// ---------------- fallback GRU (R3, global-flag sync) ----------------
__global__ void __launch_bounds__(512, 1) gru_flags(
    const float* __restrict__ whh_f, const float* __restrict__ bhh_f,
    const float* __restrict__ whh_b, const float* __restrict__ bhh_b,
    float* __restrict__ out)
{
    const int dir = blockIdx.x >> 5, cta = blockIdx.x & 31;
    const int wrp = threadIdx.x >> 5, lane = threadIdx.x & 31;
    const int j = cta * 16 + wrp;
    const float* whh = dir ? whh_b : whh_f;
    const float* bhh = dir ? bhh_b : bhh_f;
    const float* gi  = dir ? g_gi_b : g_gi_f;

    float wr[16], wz[16], wn[16];
#pragma unroll
    for (int i = 0; i < 16; i++) {
        int k = lane + 32 * i;
        wr[i] = whh[(size_t)j * HH + k];
        wz[i] = whh[(size_t)(HH + j) * HH + k];
        wn[i] = whh[(size_t)(2 * HH + j) * HH + k];
    }
    const float bhr = bhh[j], bhz = bhh[HH + j], bhn = bhh[2 * HH + j];

    for (int s = 0; s < LL; s++) {
        const int t = dir ? (LL - 1 - s) : s;
        float giR = 0.f, giZ = 0.f, giN = 0.f;
        if (lane == 0) {
            const float* gt = gi + (size_t)t * (3 * HH);
            giR = __ldg(&gt[j]); giZ = __ldg(&gt[HH + j]); giN = __ldg(&gt[2 * HH + j]);
        }
        if (s > 0 && wrp == 0) {
            const unsigned tgt = (unsigned)s;
            while (__any_sync(0xffffffffu, ld_acq(&g_flag[dir][lane][0]) < tgt)) {}
        }
        __syncthreads();
        const float* hp = g_h[dir][s & 1];
        float* hn = g_h[dir][(s + 1) & 1];
        float aR = 0.f, aZ = 0.f, aN = 0.f;
#pragma unroll
        for (int i = 0; i < 16; i++) {
            float hv = __ldcg(&hp[lane + 32 * i]);
            aR = fmaf(wr[i], hv, aR);
            aZ = fmaf(wz[i], hv, aZ);
            aN = fmaf(wn[i], hv, aN);
        }
#pragma unroll
        for (int o = 16; o; o >>= 1) {
            aR += __shfl_xor_sync(0xffffffffu, aR, o);
            aZ += __shfl_xor_sync(0xffffffffu, aZ, o);
            aN += __shfl_xor_sync(0xffffffffu, aN, o);
        }
        if (lane == 0) {
            float r = sigm_(giR + aR + bhr);
            float z = sigm_(giZ + aZ + bhz);
            float n = tanh_(giN + r * (aN + bhn));
            float hprev = __ldcg(&hp[j]);
            float hnew = (1.f - z) * n + z * hprev;
            __stcg(&hn[j], hnew);
            out[(size_t)t * (2 * HH) + dir * HH + j] = hnew;
        }
        __syncthreads();
        if (threadIdx.x == 0) st_rel(&g_flag[dir][cta][0], (unsigned)(s + 1));
    }
}

// ---------------- launch ----------------
extern "C" void kernel_launch(void* const* d_in, const int* in_sizes, int n_in,
                              void* d_out, int out_size) {
    const float* v     = (const float*)d_in[0];
    const float* w1    = (const float*)d_in[1];
    const float* b1    = (const float*)d_in[2];
    const float* w2    = (const float*)d_in[3];
    const float* b2    = (const float*)d_in[4];
    const float* wih_f = (const float*)d_in[5];
    const float* whh_f = (const float*)d_in[6];
    const float* bih_f = (const float*)d_in[7];
    const float* bhh_f = (const float*)d_in[8];
    const float* wih_b = (const float*)d_in[9];
    const float* whh_b = (const float*)d_in[10];
    const float* bih_b = (const float*)d_in[11];
    const float* bhh_b = (const float*)d_in[12];
    float* out = (float*)d_out;

    init_zero<<<2, 1024>>>();
    gemm_uw<<<dim3(8, 8, 2), 256>>>(v, w1, b1, w2, b2);
    attn_e<<<dim3(16, 32), dim3(32, 16)>>>(v);
    softmax_rows<<<512, 512>>>();
    gemm_c<<<dim3(8, 8), 256>>>(v);
    gemm_gi<<<dim3(24, 8, 2), 256>>>(v, wih_f, bih_f, wih_b, bih_b);

    // Try 16-CTA cluster path; fall back to flag-sync scan.
    cudaFuncSetAttribute((const void*)gru_cluster,
                         cudaFuncAttributeNonPortableClusterSizeAllowed, 1);
    cudaLaunchConfig_t cfg = {};
    cfg.gridDim = dim3(32, 1, 1);
    cfg.blockDim = dim3(512, 1, 1);
    cfg.dynamicSmemBytes = 0;
    cfg.stream = 0;
    cudaLaunchAttribute attrs[1];
    attrs[0].id = cudaLaunchAttributeClusterDimension;
    attrs[0].val.clusterDim = {16, 1, 1};
    cfg.attrs = attrs;
    cfg.numAttrs = 1;

    int nclus = 0;
    cudaError_t qe = cudaOccupancyMaxActiveClusters(&nclus, gru_cluster, &cfg);
    bool ok = (qe == cudaSuccess && nclus >= 2);
    if (ok) {
        cudaError_t le = cudaLaunchKernelEx(&cfg, gru_cluster,
                                            whh_f, bhh_f, whh_b, bhh_b, out);
        if (le != cudaSuccess) ok = false;
    }
    if (!ok) {
        cudaGetLastError();  // clear any query/launch error
        gru_flags<<<64, 512>>>(whh_f, bhh_f, whh_b, bhh_b, out);
    }
}

// round 8
// speedup vs baseline: 2.9285x; 1.0328x over previous
#include <cuda_runtime.h>
#include <cuda_bf16.h>

#define LL 512
#define DD 512
#define HH 512

typedef unsigned long long ull;

// ---------------- device scratch ----------------
__device__ float g_u[LL * DD];
__device__ float g_w[LL * DD];
__device__ float g_e[LL * LL];
__device__ float g_a[LL * LL];
__device__ float g_c[LL * DD];
__device__ float g_gi_f[LL * 3 * HH];
__device__ float g_gi_b[LL * 3 * HH];
__device__ float g_h[2][2][HH];               // fallback: [dir][parity][h]
__device__ unsigned int g_flag[2][32][32];    // fallback: per-producer flag lines

__device__ __forceinline__ float sigm_(float x) {
    return __fdividef(1.f, 1.f + __expf(-x));
}
__device__ __forceinline__ float tanh_(float x) {
    return 1.f - __fdividef(2.f, __expf(x + x) + 1.f);
}
__device__ __forceinline__ unsigned int ld_acq(const unsigned int* p) {
    unsigned int v;
    asm volatile("ld.acquire.gpu.global.u32 %0, [%1];" : "=r"(v) : "l"(p) : "memory");
    return v;
}
__device__ __forceinline__ void st_rel(unsigned int* p, unsigned int v) {
    asm volatile("st.release.gpu.global.u32 [%0], %1;" :: "l"(p), "r"(v) : "memory");
}
__device__ __forceinline__ void ffma2(ull& d, ull a, ull b) {
    asm("fma.rn.f32x2 %0, %1, %2, %0;" : "+l"(d) : "l"(a), "l"(b));
}
__device__ __forceinline__ ull packff(float x) {
    ull r; asm("mov.b64 %0, {%1, %1};" : "=l"(r) : "f"(x)); return r;
}
__device__ __forceinline__ ull pack2(float x, float y) {
    ull r; asm("mov.b64 %0, {%1, %2};" : "=l"(r) : "f"(x), "f"(y)); return r;
}
__device__ __forceinline__ float2 unpk(ull v) {
    float2 f; asm("mov.b64 {%0, %1}, %2;" : "=f"(f.x), "=f"(f.y) : "l"(v)); return f;
}
__device__ __forceinline__ unsigned smem_u32(const void* p) {
    unsigned a;
    asm("{ .reg .u64 t; cvta.to.shared.u64 t, %1; cvt.u32.u64 %0, t; }" : "=r"(a) : "l"(p));
    return a;
}
__device__ __forceinline__ unsigned ctarank_() {
    unsigned r; asm("mov.u32 %0, %%cluster_ctarank;" : "=r"(r)); return r;
}

// ---------------- init (zero fallback h + flags) ----------------
__global__ void init_zero() {
    int i = blockIdx.x * 1024 + threadIdx.x;
    if (i < 2048) ((unsigned int*)g_flag)[i] = 0u;
    if (i < 2048) ((float*)g_h)[i] = 0.f;
}

// ---------------- GEMM core (f32x2 packed) ----------------
__device__ __forceinline__ void gemm_core(
    const float* __restrict__ A0, const float* __restrict__ A1, int K0,
    const float* __restrict__ B, const float* __restrict__ bias,
    float* __restrict__ C, int N, int K, int transB)
{
    __shared__ __align__(16) float As[16][68];
    __shared__ __align__(16) float Bs[16][68];
    const int tid = threadIdx.x;
    const int m0 = blockIdx.y * 64, n0 = blockIdx.x * 64;
    const int tm = (tid >> 4) * 4, tn = (tid & 15) * 4;
    const int K1 = K - K0;
    ull acc[4][2] = {};
    for (int k0 = 0; k0 < K; k0 += 16) {
#pragma unroll
        for (int i = 0; i < 4; i++) {
            int e = tid + 256 * i;
            {
                int kk = e & 15, row = e >> 4, gk = k0 + kk;
                As[kk][row] = (gk < K0) ? A0[(m0 + row) * K0 + gk]
                                        : A1[(m0 + row) * K1 + gk - K0];
            }
            if (transB) {
                int kk = e & 15, row = e >> 4;
                Bs[kk][row] = B[(size_t)(n0 + row) * K + k0 + kk];
            } else {
                int n = e & 63, kk = e >> 6;
                Bs[kk][n] = B[(size_t)(k0 + kk) * N + n0 + n];
            }
        }
        __syncthreads();
#pragma unroll
        for (int kk = 0; kk < 16; kk++) {
            float4 a = *(const float4*)&As[kk][tm];
            const ull* bp = (const ull*)&Bs[kk][tn];
            ull b01 = bp[0], b23 = bp[1];
            ull a0 = packff(a.x), a1 = packff(a.y), a2 = packff(a.z), a3 = packff(a.w);
            ffma2(acc[0][0], a0, b01); ffma2(acc[0][1], a0, b23);
            ffma2(acc[1][0], a1, b01); ffma2(acc[1][1], a1, b23);
            ffma2(acc[2][0], a2, b01); ffma2(acc[2][1], a2, b23);
            ffma2(acc[3][0], a3, b01); ffma2(acc[3][1], a3, b23);
        }
        __syncthreads();
    }
#pragma unroll
    for (int i = 0; i < 4; i++) {
        float2 c01 = unpk(acc[i][0]), c23 = unpk(acc[i][1]);
        float* cp = C + (size_t)(m0 + tm + i) * N + n0 + tn;
        float b0 = 0.f, b1 = 0.f, b2 = 0.f, b3 = 0.f;
        if (bias) { b0 = bias[n0+tn]; b1 = bias[n0+tn+1]; b2 = bias[n0+tn+2]; b3 = bias[n0+tn+3]; }
        cp[0] = c01.x + b0; cp[1] = c01.y + b1; cp[2] = c23.x + b2; cp[3] = c23.y + b3;
    }
}

__global__ void gemm_uw(const float* __restrict__ v,
                        const float* __restrict__ w1, const float* __restrict__ b1,
                        const float* __restrict__ w2, const float* __restrict__ b2) {
    if (blockIdx.z == 0) gemm_core(v, v, 512, w1, b1, g_u, 512, 512, 1);
    else                 gemm_core(v, v, 512, w2, b2, g_w, 512, 512, 1);
}
__global__ void gemm_c(const float* __restrict__ v) {
    gemm_core(g_a, g_a, 512, v, nullptr, g_c, 512, 512, 0);
}
__global__ void gemm_gi(const float* __restrict__ v,
                        const float* __restrict__ wf, const float* __restrict__ bf,
                        const float* __restrict__ wb, const float* __restrict__ bb) {
    if (blockIdx.z == 0) gemm_core(v, g_c, 512, wf, bf, g_gi_f, 1536, 1024, 1);
    else                 gemm_core(v, g_c, 512, wb, bb, g_gi_b, 1536, 1024, 1);
}

// ---------------- attn e ----------------
__global__ void attn_e(const float* __restrict__ v) {
    __shared__ float us[32][33], vs[32][33], ws[16][33];
    const int tx = threadIdx.x, ty = threadIdx.y;
    const int j0 = blockIdx.x * 32, t0 = blockIdx.y * 16;
    float acc = 0.f;
    for (int d0 = 0; d0 < DD; d0 += 32) {
        us[ty][tx]      = g_u[(j0 + ty) * DD + d0 + tx];
        us[ty + 16][tx] = g_u[(j0 + ty + 16) * DD + d0 + tx];
        vs[ty][tx]      = v[(j0 + ty) * DD + d0 + tx];
        vs[ty + 16][tx] = v[(j0 + ty + 16) * DD + d0 + tx];
        ws[ty][tx]      = g_w[(t0 + ty) * DD + d0 + tx];
        __syncthreads();
#pragma unroll
        for (int dd = 0; dd < 32; dd++) {
            float x = us[tx][dd] + ws[ty][dd];
            float th = 1.f - __fdividef(2.f, __expf(x + x) + 1.f);
            acc = fmaf(th, vs[tx][dd], acc);
        }
        __syncthreads();
    }
    g_e[(t0 + ty) * LL + j0 + tx] = acc;
}

// ---------------- softmax rows ----------------
__global__ void softmax_rows() {
    __shared__ float red[16];
    __shared__ float bval;
    const int t = blockIdx.x, tid = threadIdx.x, w = tid >> 5, l = tid & 31;
    float x = g_e[t * LL + tid];
    float m = x;
#pragma unroll
    for (int o = 16; o; o >>= 1) m = fmaxf(m, __shfl_xor_sync(~0u, m, o));
    if (l == 0) red[w] = m;
    __syncthreads();
    if (tid == 0) {
        float mm = red[0];
#pragma unroll
        for (int i = 1; i < 16; i++) mm = fmaxf(mm, red[i]);
        bval = mm;
    }
    __syncthreads();
    float p = __expf(x - bval);
    float s = p;
#pragma unroll
    for (int o = 16; o; o >>= 1) s += __shfl_xor_sync(~0u, s, o);
    if (l == 0) red[w] = s;
    __syncthreads();
    if (tid == 0) {
        float ss = red[0];
#pragma unroll
        for (int i = 1; i < 16; i++) ss += red[i];
        bval = ss;
    }
    __syncthreads();
    g_a[t * LL + tid] = __fdividef(p, bval);
}

// ======== GRU scan: 16-CTA cluster, DSMEM h, split cluster barrier ========
// grid 32, cluster 16 -> 2 clusters (dir 0/1). Warp owns h {j0, j0+1}.
// arrive right after DSMEM publish; wait deferred to next step after gi issue.
__global__ void __launch_bounds__(512, 1) gru_cluster(
    const float* __restrict__ whh_f, const float* __restrict__ bhh_f,
    const float* __restrict__ whh_b, const float* __restrict__ bhh_b,
    float* __restrict__ out)
{
    __shared__ __align__(16) float hbuf[2][HH];
    const int dir = blockIdx.x >> 4;
    const unsigned rank = ctarank_();
    const int wrp = threadIdx.x >> 5, lane = threadIdx.x & 31;
    const int j0 = (int)rank * 32 + wrp * 2;
    const int myj = j0 + (lane & 1);
    const float* whh = dir ? whh_b : whh_f;
    const float* bhh = dir ? bhh_b : bhh_f;
    const float* gi  = dir ? g_gi_b : g_gi_f;
    float* outp = out + dir * HH;

    ull wt[3][16];
#pragma unroll
    for (int g = 0; g < 3; g++) {
        const float* r0 = whh + ((size_t)(g * HH + j0)) * HH + lane * 16;
        const float* r1 = r0 + HH;
#pragma unroll
        for (int c = 0; c < 16; c++) wt[g][c] = pack2(r0[c], r1[c]);
    }
    const float bR = bhh[myj], bZ = bhh[HH + myj], bN = bhh[2 * HH + myj];

    for (int i = threadIdx.x; i < HH; i += 512) hbuf[0][i] = 0.f;
    const unsigned sb0 = smem_u32(&hbuf[0][0]);
    const unsigned sb1 = smem_u32(&hbuf[1][0]);
    __syncthreads();
    asm volatile("barrier.cluster.arrive.aligned;" ::: "memory");

    for (int s = 0; s < LL; s++) {
        const int t = dir ? (LL - 1 - s) : s;
        // gi loads (independent of h) issue before the wait
        float giR = 0.f, giZ = 0.f, giN = 0.f;
        if (lane < 2) {
            const float* gt = gi + (size_t)t * (3 * HH);
            giR = __ldg(gt + myj); giZ = __ldg(gt + HH + myj); giN = __ldg(gt + 2 * HH + myj);
        }
        // wait for h_s publication (arrive happened at end of previous step)
        asm volatile("barrier.cluster.wait.aligned;" ::: "memory");
        const float* hp = hbuf[s & 1];
        ull aR = 0, aZ = 0, aN = 0;
#pragma unroll
        for (int c4 = 0; c4 < 4; c4++) {
            float4 hv = *(const float4*)(hp + lane * 16 + c4 * 4);
            ull h0 = packff(hv.x), h1 = packff(hv.y), h2 = packff(hv.z), h3 = packff(hv.w);
            ffma2(aR, wt[0][c4*4+0], h0); ffma2(aZ, wt[1][c4*4+0], h0); ffma2(aN, wt[2][c4*4+0], h0);
            ffma2(aR, wt[0][c4*4+1], h1); ffma2(aZ, wt[1][c4*4+1], h1); ffma2(aN, wt[2][c4*4+1], h1);
            ffma2(aR, wt[0][c4*4+2], h2); ffma2(aZ, wt[1][c4*4+2], h2); ffma2(aN, wt[2][c4*4+2], h2);
            ffma2(aR, wt[0][c4*4+3], h3); ffma2(aZ, wt[1][c4*4+3], h3); ffma2(aN, wt[2][c4*4+3], h3);
        }
        float2 fR = unpk(aR), fZ = unpk(aZ), fN = unpk(aN);
#pragma unroll
        for (int o = 16; o; o >>= 1) {
            fR.x += __shfl_xor_sync(~0u, fR.x, o);
            fR.y += __shfl_xor_sync(~0u, fR.y, o);
            fZ.x += __shfl_xor_sync(~0u, fZ.x, o);
            fZ.y += __shfl_xor_sync(~0u, fZ.y, o);
            fN.x += __shfl_xor_sync(~0u, fN.x, o);
            fN.y += __shfl_xor_sync(~0u, fN.y, o);
        }
        float hnew = 0.f;
        if (lane < 2) {
            float aRs = lane ? fR.y : fR.x;
            float aZs = lane ? fZ.y : fZ.x;
            float aNs = lane ? fN.y : fN.x;
            float rr = sigm_(giR + aRs + bR);
            float zz = sigm_(giZ + aZs + bZ);
            float nn = tanh_(giN + rr * (aNs + bN));
            float hprev = hp[myj];
            hnew = (1.f - zz) * nn + zz * hprev;
        }
        // publish h_{s+1}: one cluster store per lane (rank = lane>>1), then arrive
        float hv2 = __shfl_sync(0xffffffffu, hnew, lane & 1);
        unsigned laddr = (((s + 1) & 1) ? sb1 : sb0) + (unsigned)myj * 4u;
        unsigned raddr;
        asm("mapa.shared::cluster.u32 %0, %1, %2;" : "=r"(raddr) : "r"(laddr), "r"(lane >> 1));
        asm volatile("st.shared::cluster.f32 [%0], %1;" :: "r"(raddr), "f"(hv2) : "memory");
        asm volatile("barrier.cluster.arrive.aligned;" ::: "memory");
        // out store off the handshake critical path
        if (lane < 2) outp[(size_t)t * (2 * HH) + myj] = hnew;
    }
    asm volatile("barrier.cluster.wait.aligned;" ::: "memory");
}

// ---------------- fallback GRU (R3, global-flag sync) ----------------
__global__ void __launch_bounds__(512, 1) gru_flags(
    const float* __restrict__ whh_f, const float* __restrict__ bhh_f,
    const float* __restrict__ whh_b, const float* __restrict__ bhh_b,
    float* __restrict__ out)
{
    const int dir = blockIdx.x >> 5, cta = blockIdx.x & 31;
    const int wrp = threadIdx.x >> 5, lane = threadIdx.x & 31;
    const int j = cta * 16 + wrp;
    const float* whh = dir ? whh_b : whh_f;
    const float* bhh = dir ? bhh_b : bhh_f;
    const float* gi  = dir ? g_gi_b : g_gi_f;

    float wr[16], wz[16], wn[16];
#pragma unroll
    for (int i = 0; i < 16; i++) {
        int k = lane + 32 * i;
        wr[i] = whh[(size_t)j * HH + k];
        wz[i] = whh[(size_t)(HH + j) * HH + k];
        wn[i] = whh[(size_t)(2 * HH + j) * HH + k];
    }
    const float bhr = bhh[j], bhz = bhh[HH + j], bhn = bhh[2 * HH + j];

    for (int s = 0; s < LL; s++) {
        const int t = dir ? (LL - 1 - s) : s;
        float giR = 0.f, giZ = 0.f, giN = 0.f;
        if (lane == 0) {
            const float* gt = gi + (size_t)t * (3 * HH);
            giR = __ldg(&gt[j]); giZ = __ldg(&gt[HH + j]); giN = __ldg(&gt[2 * HH + j]);
        }
        if (s > 0 && wrp == 0) {
            const unsigned tgt = (unsigned)s;
            while (__any_sync(0xffffffffu, ld_acq(&g_flag[dir][lane][0]) < tgt)) {}
        }
        __syncthreads();
        const float* hp = g_h[dir][s & 1];
        float* hn = g_h[dir][(s + 1) & 1];
        float aR = 0.f, aZ = 0.f, aN = 0.f;
#pragma unroll
        for (int i = 0; i < 16; i++) {
            float hv = __ldcg(&hp[lane + 32 * i]);
            aR = fmaf(wr[i], hv, aR);
            aZ = fmaf(wz[i], hv, aZ);
            aN = fmaf(wn[i], hv, aN);
        }
#pragma unroll
        for (int o = 16; o; o >>= 1) {
            aR += __shfl_xor_sync(0xffffffffu, aR, o);
            aZ += __shfl_xor_sync(0xffffffffu, aZ, o);
            aN += __shfl_xor_sync(0xffffffffu, aN, o);
        }
        if (lane == 0) {
            float r = sigm_(giR + aR + bhr);
            float z = sigm_(giZ + aZ + bhz);
            float n = tanh_(giN + r * (aN + bhn));
            float hprev = __ldcg(&hp[j]);
            float hnew = (1.f - z) * n + z * hprev;
            __stcg(&hn[j], hnew);
            out[(size_t)t * (2 * HH) + dir * HH + j] = hnew;
        }
        __syncthreads();
        if (threadIdx.x == 0) st_rel(&g_flag[dir][cta][0], (unsigned)(s + 1));
    }
}

// ---------------- launch ----------------
extern "C" void kernel_launch(void* const* d_in, const int* in_sizes, int n_in,
                              void* d_out, int out_size) {
    const float* v     = (const float*)d_in[0];
    const float* w1    = (const float*)d_in[1];
    const float* b1    = (const float*)d_in[2];
    const float* w2    = (const float*)d_in[3];
    const float* b2    = (const float*)d_in[4];
    const float* wih_f = (const float*)d_in[5];
    const float* whh_f = (const float*)d_in[6];
    const float* bih_f = (const float*)d_in[7];
    const float* bhh_f = (const float*)d_in[8];
    const float* wih_b = (const float*)d_in[9];
    const float* whh_b = (const float*)d_in[10];
    const float* bih_b = (const float*)d_in[11];
    const float* bhh_b = (const float*)d_in[12];
    float* out = (float*)d_out;

    init_zero<<<2, 1024>>>();
    gemm_uw<<<dim3(8, 8, 2), 256>>>(v, w1, b1, w2, b2);
    attn_e<<<dim3(16, 32), dim3(32, 16)>>>(v);
    softmax_rows<<<512, 512>>>();
    gemm_c<<<dim3(8, 8), 256>>>(v);
    gemm_gi<<<dim3(24, 8, 2), 256>>>(v, wih_f, bih_f, wih_b, bih_b);

    cudaFuncSetAttribute((const void*)gru_cluster,
                         cudaFuncAttributeNonPortableClusterSizeAllowed, 1);
    cudaLaunchConfig_t cfg = {};
    cfg.gridDim = dim3(32, 1, 1);
    cfg.blockDim = dim3(512, 1, 1);
    cfg.dynamicSmemBytes = 0;
    cfg.stream = 0;
    cudaLaunchAttribute attrs[1];
    attrs[0].id = cudaLaunchAttributeClusterDimension;
    attrs[0].val.clusterDim = {16, 1, 1};
    cfg.attrs = attrs;
    cfg.numAttrs = 1;

    int nclus = 0;
    cudaError_t qe = cudaOccupancyMaxActiveClusters(&nclus, gru_cluster, &cfg);
    bool ok = (qe == cudaSuccess && nclus >= 2);
    if (ok) {
        cudaError_t le = cudaLaunchKernelEx(&cfg, gru_cluster,
                                            whh_f, bhh_f, whh_b, bhh_b, out);
        if (le != cudaSuccess) ok = false;
    }
    if (!ok) {
        cudaGetLastError();
        gru_flags<<<64, 512>>>(whh_f, bhh_f, whh_b, bhh_b, out);
    }
}

// round 9
// speedup vs baseline: 3.1639x; 1.0804x over previous
#include <cuda_runtime.h>
#include <cuda_bf16.h>

#define LL 512
#define DD 512
#define HH 512

typedef unsigned long long ull;

// ---------------- device scratch ----------------
__device__ float g_u[LL * DD];
__device__ float g_w[LL * DD];
__device__ float g_e[LL * LL];
__device__ float g_a[LL * LL];
__device__ float g_c[LL * DD];
__device__ float g_gi_f[LL * 3 * HH];
__device__ float g_gi_b[LL * 3 * HH];
__device__ float g_h[2][2][HH];               // fallback: [dir][parity][h]
__device__ unsigned int g_flag[2][32][32];    // fallback: per-producer flag lines

__device__ __forceinline__ float sigm_(float x) {
    return __fdividef(1.f, 1.f + __expf(-x));
}
__device__ __forceinline__ float tanh_(float x) {
    return 1.f - __fdividef(2.f, __expf(x + x) + 1.f);
}
__device__ __forceinline__ unsigned int ld_acq(const unsigned int* p) {
    unsigned int v;
    asm volatile("ld.acquire.gpu.global.u32 %0, [%1];" : "=r"(v) : "l"(p) : "memory");
    return v;
}
__device__ __forceinline__ void st_rel(unsigned int* p, unsigned int v) {
    asm volatile("st.release.gpu.global.u32 [%0], %1;" :: "l"(p), "r"(v) : "memory");
}
__device__ __forceinline__ void ffma2(ull& d, ull a, ull b) {
    asm("fma.rn.f32x2 %0, %1, %2, %0;" : "+l"(d) : "l"(a), "l"(b));
}
__device__ __forceinline__ ull packff(float x) {
    ull r; asm("mov.b64 %0, {%1, %1};" : "=l"(r) : "f"(x)); return r;
}
__device__ __forceinline__ ull pack2(float x, float y) {
    ull r; asm("mov.b64 %0, {%1, %2};" : "=l"(r) : "f"(x), "f"(y)); return r;
}
__device__ __forceinline__ float2 unpk(ull v) {
    float2 f; asm("mov.b64 {%0, %1}, %2;" : "=f"(f.x), "=f"(f.y) : "l"(v)); return f;
}
__device__ __forceinline__ unsigned smem_u32(const void* p) {
    unsigned a;
    asm("{ .reg .u64 t; cvta.to.shared.u64 t, %1; cvt.u32.u64 %0, t; }" : "=r"(a) : "l"(p));
    return a;
}
__device__ __forceinline__ unsigned ctarank_() {
    unsigned r; asm("mov.u32 %0, %%cluster_ctarank;" : "=r"(r)); return r;
}
// stock acquire.cta parity wait (same as TMA-consumer pattern)
__device__ __forceinline__ void mbar_wait(unsigned addr, unsigned parity) {
    asm volatile(
        "{\n\t"
        ".reg .pred P;\n\t"
        "WL_%=:\n\t"
        "mbarrier.try_wait.parity.acquire.cta.shared::cta.b64 P, [%0], %1, 0x989680;\n\t"
        "@!P bra WL_%=;\n\t"
        "}"
        :: "r"(addr), "r"(parity) : "memory");
}

// ---------------- init (zero fallback h + flags) ----------------
__global__ void init_zero() {
    int i = blockIdx.x * 1024 + threadIdx.x;
    if (i < 2048) ((unsigned int*)g_flag)[i] = 0u;
    if (i < 2048) ((float*)g_h)[i] = 0.f;
}

// ---------------- GEMM core (f32x2 packed) ----------------
__device__ __forceinline__ void gemm_core(
    const float* __restrict__ A0, const float* __restrict__ A1, int K0,
    const float* __restrict__ B, const float* __restrict__ bias,
    float* __restrict__ C, int N, int K, int transB)
{
    __shared__ __align__(16) float As[16][68];
    __shared__ __align__(16) float Bs[16][68];
    const int tid = threadIdx.x;
    const int m0 = blockIdx.y * 64, n0 = blockIdx.x * 64;
    const int tm = (tid >> 4) * 4, tn = (tid & 15) * 4;
    const int K1 = K - K0;
    ull acc[4][2] = {};
    for (int k0 = 0; k0 < K; k0 += 16) {
#pragma unroll
        for (int i = 0; i < 4; i++) {
            int e = tid + 256 * i;
            {
                int kk = e & 15, row = e >> 4, gk = k0 + kk;
                As[kk][row] = (gk < K0) ? A0[(m0 + row) * K0 + gk]
                                        : A1[(m0 + row) * K1 + gk - K0];
            }
            if (transB) {
                int kk = e & 15, row = e >> 4;
                Bs[kk][row] = B[(size_t)(n0 + row) * K + k0 + kk];
            } else {
                int n = e & 63, kk = e >> 6;
                Bs[kk][n] = B[(size_t)(k0 + kk) * N + n0 + n];
            }
        }
        __syncthreads();
#pragma unroll
        for (int kk = 0; kk < 16; kk++) {
            float4 a = *(const float4*)&As[kk][tm];
            const ull* bp = (const ull*)&Bs[kk][tn];
            ull b01 = bp[0], b23 = bp[1];
            ull a0 = packff(a.x), a1 = packff(a.y), a2 = packff(a.z), a3 = packff(a.w);
            ffma2(acc[0][0], a0, b01); ffma2(acc[0][1], a0, b23);
            ffma2(acc[1][0], a1, b01); ffma2(acc[1][1], a1, b23);
            ffma2(acc[2][0], a2, b01); ffma2(acc[2][1], a2, b23);
            ffma2(acc[3][0], a3, b01); ffma2(acc[3][1], a3, b23);
        }
        __syncthreads();
    }
#pragma unroll
    for (int i = 0; i < 4; i++) {
        float2 c01 = unpk(acc[i][0]), c23 = unpk(acc[i][1]);
        float* cp = C + (size_t)(m0 + tm + i) * N + n0 + tn;
        float b0 = 0.f, b1 = 0.f, b2 = 0.f, b3 = 0.f;
        if (bias) { b0 = bias[n0+tn]; b1 = bias[n0+tn+1]; b2 = bias[n0+tn+2]; b3 = bias[n0+tn+3]; }
        cp[0] = c01.x + b0; cp[1] = c01.y + b1; cp[2] = c23.x + b2; cp[3] = c23.y + b3;
    }
}

__global__ void gemm_uw(const float* __restrict__ v,
                        const float* __restrict__ w1, const float* __restrict__ b1,
                        const float* __restrict__ w2, const float* __restrict__ b2) {
    if (blockIdx.z == 0) gemm_core(v, v, 512, w1, b1, g_u, 512, 512, 1);
    else                 gemm_core(v, v, 512, w2, b2, g_w, 512, 512, 1);
}
__global__ void gemm_c(const float* __restrict__ v) {
    gemm_core(g_a, g_a, 512, v, nullptr, g_c, 512, 512, 0);
}
__global__ void gemm_gi(const float* __restrict__ v,
                        const float* __restrict__ wf, const float* __restrict__ bf,
                        const float* __restrict__ wb, const float* __restrict__ bb) {
    if (blockIdx.z == 0) gemm_core(v, g_c, 512, wf, bf, g_gi_f, 1536, 1024, 1);
    else                 gemm_core(v, g_c, 512, wb, bb, g_gi_b, 1536, 1024, 1);
}

// ---------------- attn e ----------------
__global__ void attn_e(const float* __restrict__ v) {
    __shared__ float us[32][33], vs[32][33], ws[16][33];
    const int tx = threadIdx.x, ty = threadIdx.y;
    const int j0 = blockIdx.x * 32, t0 = blockIdx.y * 16;
    float acc = 0.f;
    for (int d0 = 0; d0 < DD; d0 += 32) {
        us[ty][tx]      = g_u[(j0 + ty) * DD + d0 + tx];
        us[ty + 16][tx] = g_u[(j0 + ty + 16) * DD + d0 + tx];
        vs[ty][tx]      = v[(j0 + ty) * DD + d0 + tx];
        vs[ty + 16][tx] = v[(j0 + ty + 16) * DD + d0 + tx];
        ws[ty][tx]      = g_w[(t0 + ty) * DD + d0 + tx];
        __syncthreads();
#pragma unroll
        for (int dd = 0; dd < 32; dd++) {
            float x = us[tx][dd] + ws[ty][dd];
            float th = 1.f - __fdividef(2.f, __expf(x + x) + 1.f);
            acc = fmaf(th, vs[tx][dd], acc);
        }
        __syncthreads();
    }
    g_e[(t0 + ty) * LL + j0 + tx] = acc;
}

// ---------------- softmax rows ----------------
__global__ void softmax_rows() {
    __shared__ float red[16];
    __shared__ float bval;
    const int t = blockIdx.x, tid = threadIdx.x, w = tid >> 5, l = tid & 31;
    float x = g_e[t * LL + tid];
    float m = x;
#pragma unroll
    for (int o = 16; o; o >>= 1) m = fmaxf(m, __shfl_xor_sync(~0u, m, o));
    if (l == 0) red[w] = m;
    __syncthreads();
    if (tid == 0) {
        float mm = red[0];
#pragma unroll
        for (int i = 1; i < 16; i++) mm = fmaxf(mm, red[i]);
        bval = mm;
    }
    __syncthreads();
    float p = __expf(x - bval);
    float s = p;
#pragma unroll
    for (int o = 16; o; o >>= 1) s += __shfl_xor_sync(~0u, s, o);
    if (l == 0) red[w] = s;
    __syncthreads();
    if (tid == 0) {
        float ss = red[0];
#pragma unroll
        for (int i = 1; i < 16; i++) ss += red[i];
        bval = ss;
    }
    __syncthreads();
    g_a[t * LL + tid] = __fdividef(p, bval);
}

// ======== GRU scan: 16-CTA cluster, st.async DSMEM publish + mbarrier tx ========
// grid 32, cluster 16 -> 2 clusters (dir 0/1). Warp owns h {j0, j0+1}.
// No cluster barrier in the loop: producers st.async each h value to every CTA's
// hbuf with complete_tx on that CTA's mbar; phase flips at 2048 bytes (512 floats).
__global__ void __launch_bounds__(512, 1) gru_cluster(
    const float* __restrict__ whh_f, const float* __restrict__ bhh_f,
    const float* __restrict__ whh_b, const float* __restrict__ bhh_b,
    float* __restrict__ out)
{
    __shared__ __align__(16) float hbuf[2][HH];
    __shared__ __align__(8) ull mb[2];
    const int dir = blockIdx.x >> 4;
    const int wrp = threadIdx.x >> 5, lane = threadIdx.x & 31;
    const unsigned rank = ctarank_();
    const int j0 = (int)rank * 32 + wrp * 2;
    const int myj = j0 + (lane & 1);
    const float* whh = dir ? whh_b : whh_f;
    const float* bhh = dir ? bhh_b : bhh_f;
    const float* gi  = dir ? g_gi_b : g_gi_f;
    float* outp = out + dir * HH;

    ull wt[3][16];
#pragma unroll
    for (int g = 0; g < 3; g++) {
        const float* r0 = whh + ((size_t)(g * HH + j0)) * HH + lane * 16;
        const float* r1 = r0 + HH;
#pragma unroll
        for (int c = 0; c < 16; c++) wt[g][c] = pack2(r0[c], r1[c]);
    }
    const float bR = bhh[myj], bZ = bhh[HH + myj], bN = bhh[2 * HH + myj];

    for (int i = threadIdx.x; i < HH; i += 512) hbuf[0][i] = 0.f;
    const unsigned sb0 = smem_u32(&hbuf[0][0]);
    const unsigned sb1 = smem_u32(&hbuf[1][0]);
    const unsigned mb0 = smem_u32(&mb[0]);
    const unsigned mb1 = smem_u32(&mb[1]);
    if (threadIdx.x == 0) {
        asm volatile("mbarrier.init.shared.b64 [%0], %1;" :: "r"(mb0), "r"(1u) : "memory");
        asm volatile("mbarrier.init.shared.b64 [%0], %1;" :: "r"(mb1), "r"(1u) : "memory");
        // arm both slots (h_1 -> mb1, h_2 -> mb0)
        asm volatile("mbarrier.arrive.expect_tx.shared.b64 _, [%0], %1;"
                     :: "r"(mb0), "r"(2048u) : "memory");
        asm volatile("mbarrier.arrive.expect_tx.shared.b64 _, [%0], %1;"
                     :: "r"(mb1), "r"(2048u) : "memory");
    }
    __syncthreads();
    asm volatile("barrier.cluster.arrive.aligned;" ::: "memory");
    asm volatile("barrier.cluster.wait.aligned;" ::: "memory");

    unsigned par[2] = {0u, 0u};
    for (int s = 0; s < LL; s++) {
        const int t = dir ? (LL - 1 - s) : s;
        // gi loads (independent of h) issue before the wait
        float giR = 0.f, giZ = 0.f, giN = 0.f;
        if (lane < 2) {
            const float* gt = gi + (size_t)t * (3 * HH);
            giR = __ldg(gt + myj); giZ = __ldg(gt + HH + myj); giN = __ldg(gt + 2 * HH + myj);
        }
        const int sl = s & 1;
        const unsigned mcur = sl ? mb1 : mb0;
        if (s > 0) {
            mbar_wait(mcur, par[sl]);
            par[sl] ^= 1;
            // re-arm this slot for h_{s+2}; must precede our h_{s+1} stores
            if (threadIdx.x == 0)
                asm volatile("mbarrier.arrive.expect_tx.shared.b64 _, [%0], %1;"
                             :: "r"(mcur), "r"(2048u) : "memory");
            __syncthreads();
        }
        const float* hp = hbuf[sl];
        ull aR = 0, aZ = 0, aN = 0;
#pragma unroll
        for (int c4 = 0; c4 < 4; c4++) {
            float4 hv = *(const float4*)(hp + lane * 16 + c4 * 4);
            ull h0 = packff(hv.x), h1 = packff(hv.y), h2 = packff(hv.z), h3 = packff(hv.w);
            ffma2(aR, wt[0][c4*4+0], h0); ffma2(aZ, wt[1][c4*4+0], h0); ffma2(aN, wt[2][c4*4+0], h0);
            ffma2(aR, wt[0][c4*4+1], h1); ffma2(aZ, wt[1][c4*4+1], h1); ffma2(aN, wt[2][c4*4+1], h1);
            ffma2(aR, wt[0][c4*4+2], h2); ffma2(aZ, wt[1][c4*4+2], h2); ffma2(aN, wt[2][c4*4+2], h2);
            ffma2(aR, wt[0][c4*4+3], h3); ffma2(aZ, wt[1][c4*4+3], h3); ffma2(aN, wt[2][c4*4+3], h3);
        }
        float2 fR = unpk(aR), fZ = unpk(aZ), fN = unpk(aN);
#pragma unroll
        for (int o = 16; o; o >>= 1) {
            fR.x += __shfl_xor_sync(~0u, fR.x, o);
            fR.y += __shfl_xor_sync(~0u, fR.y, o);
            fZ.x += __shfl_xor_sync(~0u, fZ.x, o);
            fZ.y += __shfl_xor_sync(~0u, fZ.y, o);
            fN.x += __shfl_xor_sync(~0u, fN.x, o);
            fN.y += __shfl_xor_sync(~0u, fN.y, o);
        }
        float hnew = 0.f;
        if (lane < 2) {
            float aRs = lane ? fR.y : fR.x;
            float aZs = lane ? fZ.y : fZ.x;
            float aNs = lane ? fN.y : fN.x;
            float rr = sigm_(giR + aRs + bR);
            float zz = sigm_(giZ + aZs + bZ);
            float nn = tanh_(giN + rr * (aNs + bN));
            float hprev = hp[myj];
            hnew = (1.f - zz) * nn + zz * hprev;
        }
        // publish h_{s+1} via st.async (data + tx in one op); skip at last step
        float hv2 = __shfl_sync(0xffffffffu, hnew, lane & 1);
        if (s + 1 < LL) {
            unsigned ldata = (((s + 1) & 1) ? sb1 : sb0) + (unsigned)myj * 4u;
            unsigned lmbar = (((s + 1) & 1) ? mb1 : mb0);
            unsigned rdata, rmbar;
            asm("mapa.shared::cluster.u32 %0, %1, %2;" : "=r"(rdata) : "r"(ldata), "r"(lane >> 1));
            asm("mapa.shared::cluster.u32 %0, %1, %2;" : "=r"(rmbar) : "r"(lmbar), "r"(lane >> 1));
            asm volatile("st.async.shared::cluster.mbarrier::complete_tx::bytes.b32 [%0], %1, [%2];"
                         :: "r"(rdata), "r"(__float_as_uint(hv2)), "r"(rmbar) : "memory");
        }
        if (lane < 2) outp[(size_t)t * (2 * HH) + myj] = hnew;
    }
    asm volatile("barrier.cluster.arrive.aligned;" ::: "memory");
    asm volatile("barrier.cluster.wait.aligned;" ::: "memory");
}

// ---------------- fallback GRU (R3, global-flag sync) ----------------
__global__ void __launch_bounds__(512, 1) gru_flags(
    const float* __restrict__ whh_f, const float* __restrict__ bhh_f,
    const float* __restrict__ whh_b, const float* __restrict__ bhh_b,
    float* __restrict__ out)
{
    const int dir = blockIdx.x >> 5, cta = blockIdx.x & 31;
    const int wrp = threadIdx.x >> 5, lane = threadIdx.x & 31;
    const int j = cta * 16 + wrp;
    const float* whh = dir ? whh_b : whh_f;
    const float* bhh = dir ? bhh_b : bhh_f;
    const float* gi  = dir ? g_gi_b : g_gi_f;

    float wr[16], wz[16], wn[16];
#pragma unroll
    for (int i = 0; i < 16; i++) {
        int k = lane + 32 * i;
        wr[i] = whh[(size_t)j * HH + k];
        wz[i] = whh[(size_t)(HH + j) * HH + k];
        wn[i] = whh[(size_t)(2 * HH + j) * HH + k];
    }
    const float bhr = bhh[j], bhz = bhh[HH + j], bhn = bhh[2 * HH + j];

    for (int s = 0; s < LL; s++) {
        const int t = dir ? (LL - 1 - s) : s;
        float giR = 0.f, giZ = 0.f, giN = 0.f;
        if (lane == 0) {
            const float* gt = gi + (size_t)t * (3 * HH);
            giR = __ldg(&gt[j]); giZ = __ldg(&gt[HH + j]); giN = __ldg(&gt[2 * HH + j]);
        }
        if (s > 0 && wrp == 0) {
            const unsigned tgt = (unsigned)s;
            while (__any_sync(0xffffffffu, ld_acq(&g_flag[dir][lane][0]) < tgt)) {}
        }
        __syncthreads();
        const float* hp = g_h[dir][s & 1];
        float* hn = g_h[dir][(s + 1) & 1];
        float aR = 0.f, aZ = 0.f, aN = 0.f;
#pragma unroll
        for (int i = 0; i < 16; i++) {
            float hv = __ldcg(&hp[lane + 32 * i]);
            aR = fmaf(wr[i], hv, aR);
            aZ = fmaf(wz[i], hv, aZ);
            aN = fmaf(wn[i], hv, aN);
        }
#pragma unroll
        for (int o = 16; o; o >>= 1) {
            aR += __shfl_xor_sync(0xffffffffu, aR, o);
            aZ += __shfl_xor_sync(0xffffffffu, aZ, o);
            aN += __shfl_xor_sync(0xffffffffu, aN, o);
        }
        if (lane == 0) {
            float r = sigm_(giR + aR + bhr);
            float z = sigm_(giZ + aZ + bhz);
            float n = tanh_(giN + r * (aN + bhn));
            float hprev = __ldcg(&hp[j]);
            float hnew = (1.f - z) * n + z * hprev;
            __stcg(&hn[j], hnew);
            out[(size_t)t * (2 * HH) + dir * HH + j] = hnew;
        }
        __syncthreads();
        if (threadIdx.x == 0) st_rel(&g_flag[dir][cta][0], (unsigned)(s + 1));
    }
}

// ---------------- launch ----------------
extern "C" void kernel_launch(void* const* d_in, const int* in_sizes, int n_in,
                              void* d_out, int out_size) {
    const float* v     = (const float*)d_in[0];
    const float* w1    = (const float*)d_in[1];
    const float* b1    = (const float*)d_in[2];
    const float* w2    = (const float*)d_in[3];
    const float* b2    = (const float*)d_in[4];
    const float* wih_f = (const float*)d_in[5];
    const float* whh_f = (const float*)d_in[6];
    const float* bih_f = (const float*)d_in[7];
    const float* bhh_f = (const float*)d_in[8];
    const float* wih_b = (const float*)d_in[9];
    const float* whh_b = (const float*)d_in[10];
    const float* bih_b = (const float*)d_in[11];
    const float* bhh_b = (const float*)d_in[12];
    float* out = (float*)d_out;

    init_zero<<<2, 1024>>>();
    gemm_uw<<<dim3(8, 8, 2), 256>>>(v, w1, b1, w2, b2);
    attn_e<<<dim3(16, 32), dim3(32, 16)>>>(v);
    softmax_rows<<<512, 512>>>();
    gemm_c<<<dim3(8, 8), 256>>>(v);
    gemm_gi<<<dim3(24, 8, 2), 256>>>(v, wih_f, bih_f, wih_b, bih_b);

    cudaFuncSetAttribute((const void*)gru_cluster,
                         cudaFuncAttributeNonPortableClusterSizeAllowed, 1);
    cudaLaunchConfig_t cfg = {};
    cfg.gridDim = dim3(32, 1, 1);
    cfg.blockDim = dim3(512, 1, 1);
    cfg.dynamicSmemBytes = 0;
    cfg.stream = 0;
    cudaLaunchAttribute attrs[1];
    attrs[0].id = cudaLaunchAttributeClusterDimension;
    attrs[0].val.clusterDim = {16, 1, 1};
    cfg.attrs = attrs;
    cfg.numAttrs = 1;

    int nclus = 0;
    cudaError_t qe = cudaOccupancyMaxActiveClusters(&nclus, gru_cluster, &cfg);
    bool ok = (qe == cudaSuccess && nclus >= 2);
    if (ok) {
        cudaError_t le = cudaLaunchKernelEx(&cfg, gru_cluster,
                                            whh_f, bhh_f, whh_b, bhh_b, out);
        if (le != cudaSuccess) ok = false;
    }
    if (!ok) {
        cudaGetLastError();
        gru_flags<<<64, 512>>>(whh_f, bhh_f, whh_b, bhh_b, out);
    }
}

// round 10
// speedup vs baseline: 3.1876x; 1.0075x over previous
#include <cuda_runtime.h>
#include <cuda_bf16.h>

#define LL 512
#define DD 512
#define HH 512

typedef unsigned long long ull;

// ---------------- device scratch ----------------
__device__ float g_u[LL * DD];
__device__ float g_w[LL * DD];
__device__ float g_e[LL * LL];
__device__ float g_a[LL * LL];
__device__ float g_c[LL * DD];
__device__ float g_gi_f[LL * 3 * HH];
__device__ float g_gi_b[LL * 3 * HH];
__device__ float g_h[2][2][HH];               // fallback: [dir][parity][h]
__device__ unsigned int g_flag[2][32][32];    // fallback: per-producer flag lines

__device__ __forceinline__ float sigm_(float x) {
    return __fdividef(1.f, 1.f + __expf(-x));
}
__device__ __forceinline__ float tanh_(float x) {
    return 1.f - __fdividef(2.f, __expf(x + x) + 1.f);
}
__device__ __forceinline__ unsigned int ld_acq(const unsigned int* p) {
    unsigned int v;
    asm volatile("ld.acquire.gpu.global.u32 %0, [%1];" : "=r"(v) : "l"(p) : "memory");
    return v;
}
__device__ __forceinline__ void st_rel(unsigned int* p, unsigned int v) {
    asm volatile("st.release.gpu.global.u32 [%0], %1;" :: "l"(p), "r"(v) : "memory");
}
__device__ __forceinline__ void ffma2(ull& d, ull a, ull b) {
    asm("fma.rn.f32x2 %0, %1, %2, %0;" : "+l"(d) : "l"(a), "l"(b));
}
__device__ __forceinline__ void addx2(ull& d, ull a) {
    asm("add.rn.f32x2 %0, %0, %1;" : "+l"(d) : "l"(a));
}
__device__ __forceinline__ ull packff(float x) {
    ull r; asm("mov.b64 %0, {%1, %1};" : "=l"(r) : "f"(x)); return r;
}
__device__ __forceinline__ ull pack2(float x, float y) {
    ull r; asm("mov.b64 %0, {%1, %2};" : "=l"(r) : "f"(x), "f"(y)); return r;
}
__device__ __forceinline__ float2 unpk(ull v) {
    float2 f; asm("mov.b64 {%0, %1}, %2;" : "=f"(f.x), "=f"(f.y) : "l"(v)); return f;
}
__device__ __forceinline__ unsigned smem_u32(const void* p) {
    unsigned a;
    asm("{ .reg .u64 t; cvta.to.shared.u64 t, %1; cvt.u32.u64 %0, t; }" : "=r"(a) : "l"(p));
    return a;
}
__device__ __forceinline__ unsigned ctarank_() {
    unsigned r; asm("mov.u32 %0, %%cluster_ctarank;" : "=r"(r)); return r;
}
__device__ __forceinline__ void mbar_wait(unsigned addr, unsigned parity) {
    asm volatile(
        "{\n\t"
        ".reg .pred P;\n\t"
        "WL_%=:\n\t"
        "mbarrier.try_wait.parity.acquire.cta.shared::cta.b64 P, [%0], %1, 0x989680;\n\t"
        "@!P bra WL_%=;\n\t"
        "}"
        :: "r"(addr), "r"(parity) : "memory");
}

// ---------------- init (zero fallback h + flags) ----------------
__global__ void init_zero() {
    int i = blockIdx.x * 1024 + threadIdx.x;
    if (i < 2048) ((unsigned int*)g_flag)[i] = 0u;
    if (i < 2048) ((float*)g_h)[i] = 0.f;
}

// ---------------- GEMM core (f32x2 packed) ----------------
__device__ __forceinline__ void gemm_core(
    const float* __restrict__ A0, const float* __restrict__ A1, int K0,
    const float* __restrict__ B, const float* __restrict__ bias,
    float* __restrict__ C, int N, int K, int transB)
{
    __shared__ __align__(16) float As[16][68];
    __shared__ __align__(16) float Bs[16][68];
    const int tid = threadIdx.x;
    const int m0 = blockIdx.y * 64, n0 = blockIdx.x * 64;
    const int tm = (tid >> 4) * 4, tn = (tid & 15) * 4;
    const int K1 = K - K0;
    ull acc[4][2] = {};
    for (int k0 = 0; k0 < K; k0 += 16) {
#pragma unroll
        for (int i = 0; i < 4; i++) {
            int e = tid + 256 * i;
            {
                int kk = e & 15, row = e >> 4, gk = k0 + kk;
                As[kk][row] = (gk < K0) ? A0[(m0 + row) * K0 + gk]
                                        : A1[(m0 + row) * K1 + gk - K0];
            }
            if (transB) {
                int kk = e & 15, row = e >> 4;
                Bs[kk][row] = B[(size_t)(n0 + row) * K + k0 + kk];
            } else {
                int n = e & 63, kk = e >> 6;
                Bs[kk][n] = B[(size_t)(k0 + kk) * N + n0 + n];
            }
        }
        __syncthreads();
#pragma unroll
        for (int kk = 0; kk < 16; kk++) {
            float4 a = *(const float4*)&As[kk][tm];
            const ull* bp = (const ull*)&Bs[kk][tn];
            ull b01 = bp[0], b23 = bp[1];
            ull a0 = packff(a.x), a1 = packff(a.y), a2 = packff(a.z), a3 = packff(a.w);
            ffma2(acc[0][0], a0, b01); ffma2(acc[0][1], a0, b23);
            ffma2(acc[1][0], a1, b01); ffma2(acc[1][1], a1, b23);
            ffma2(acc[2][0], a2, b01); ffma2(acc[2][1], a2, b23);
            ffma2(acc[3][0], a3, b01); ffma2(acc[3][1], a3, b23);
        }
        __syncthreads();
    }
#pragma unroll
    for (int i = 0; i < 4; i++) {
        float2 c01 = unpk(acc[i][0]), c23 = unpk(acc[i][1]);
        float* cp = C + (size_t)(m0 + tm + i) * N + n0 + tn;
        float b0 = 0.f, b1 = 0.f, b2 = 0.f, b3 = 0.f;
        if (bias) { b0 = bias[n0+tn]; b1 = bias[n0+tn+1]; b2 = bias[n0+tn+2]; b3 = bias[n0+tn+3]; }
        cp[0] = c01.x + b0; cp[1] = c01.y + b1; cp[2] = c23.x + b2; cp[3] = c23.y + b3;
    }
}

__global__ void gemm_uw(const float* __restrict__ v,
                        const float* __restrict__ w1, const float* __restrict__ b1,
                        const float* __restrict__ w2, const float* __restrict__ b2) {
    if (blockIdx.z == 0) gemm_core(v, v, 512, w1, b1, g_u, 512, 512, 1);
    else                 gemm_core(v, v, 512, w2, b2, g_w, 512, 512, 1);
}
__global__ void gemm_c(const float* __restrict__ v) {
    gemm_core(g_a, g_a, 512, v, nullptr, g_c, 512, 512, 0);
}
__global__ void gemm_gi(const float* __restrict__ v,
                        const float* __restrict__ wf, const float* __restrict__ bf,
                        const float* __restrict__ wb, const float* __restrict__ bb) {
    if (blockIdx.z == 0) gemm_core(v, g_c, 512, wf, bf, g_gi_f, 1536, 1024, 1);
    else                 gemm_core(v, g_c, 512, wb, bb, g_gi_b, 1536, 1024, 1);
}

// ---------------- attn e ----------------
__global__ void attn_e(const float* __restrict__ v) {
    __shared__ float us[32][33], vs[32][33], ws[16][33];
    const int tx = threadIdx.x, ty = threadIdx.y;
    const int j0 = blockIdx.x * 32, t0 = blockIdx.y * 16;
    float acc = 0.f;
    for (int d0 = 0; d0 < DD; d0 += 32) {
        us[ty][tx]      = g_u[(j0 + ty) * DD + d0 + tx];
        us[ty + 16][tx] = g_u[(j0 + ty + 16) * DD + d0 + tx];
        vs[ty][tx]      = v[(j0 + ty) * DD + d0 + tx];
        vs[ty + 16][tx] = v[(j0 + ty + 16) * DD + d0 + tx];
        ws[ty][tx]      = g_w[(t0 + ty) * DD + d0 + tx];
        __syncthreads();
#pragma unroll
        for (int dd = 0; dd < 32; dd++) {
            float x = us[tx][dd] + ws[ty][dd];
            float th = 1.f - __fdividef(2.f, __expf(x + x) + 1.f);
            acc = fmaf(th, vs[tx][dd], acc);
        }
        __syncthreads();
    }
    g_e[(t0 + ty) * LL + j0 + tx] = acc;
}

// ---------------- softmax rows ----------------
__global__ void softmax_rows() {
    __shared__ float red[16];
    __shared__ float bval;
    const int t = blockIdx.x, tid = threadIdx.x, w = tid >> 5, l = tid & 31;
    float x = g_e[t * LL + tid];
    float m = x;
#pragma unroll
    for (int o = 16; o; o >>= 1) m = fmaxf(m, __shfl_xor_sync(~0u, m, o));
    if (l == 0) red[w] = m;
    __syncthreads();
    if (tid == 0) {
        float mm = red[0];
#pragma unroll
        for (int i = 1; i < 16; i++) mm = fmaxf(mm, red[i]);
        bval = mm;
    }
    __syncthreads();
    float p = __expf(x - bval);
    float s = p;
#pragma unroll
    for (int o = 16; o; o >>= 1) s += __shfl_xor_sync(~0u, s, o);
    if (l == 0) red[w] = s;
    __syncthreads();
    if (tid == 0) {
        float ss = red[0];
#pragma unroll
        for (int i = 1; i < 16; i++) ss += red[i];
        bval = ss;
    }
    __syncthreads();
    g_a[t * LL + tid] = __fdividef(p, bval);
}

// ======== GRU scan: 16-CTA cluster, b64 st.async publish + mbarrier tx ========
// grid 32, cluster 16 -> 2 clusters (dir 0/1). Warp owns h {j0, j0+1} (j0 even).
// Publish: lanes 0-15 each send ONE packed b64 (both h values) to rank=lane.
// Consumer mbar: 256 tx-updates x 8B = 2048 bytes per step.
__global__ void __launch_bounds__(512, 1) gru_cluster(
    const float* __restrict__ whh_f, const float* __restrict__ bhh_f,
    const float* __restrict__ whh_b, const float* __restrict__ bhh_b,
    float* __restrict__ out)
{
    __shared__ __align__(16) float hbuf[2][HH];
    __shared__ __align__(8) ull mb[2];
    const int dir = blockIdx.x >> 4;
    const int wrp = threadIdx.x >> 5, lane = threadIdx.x & 31;
    const unsigned rank = ctarank_();
    const int j0 = (int)rank * 32 + wrp * 2;
    const int myj = j0 + (lane & 1);
    const float* whh = dir ? whh_b : whh_f;
    const float* bhh = dir ? bhh_b : bhh_f;
    const float* gi  = dir ? g_gi_b : g_gi_f;
    float* outp = out + dir * HH;

    ull wt[3][16];
#pragma unroll
    for (int g = 0; g < 3; g++) {
        const float* r0 = whh + ((size_t)(g * HH + j0)) * HH + lane * 16;
        const float* r1 = r0 + HH;
#pragma unroll
        for (int c = 0; c < 16; c++) wt[g][c] = pack2(r0[c], r1[c]);
    }
    const float bR = bhh[myj], bZ = bhh[HH + myj], bN = bhh[2 * HH + myj];

    for (int i = threadIdx.x; i < HH; i += 512) hbuf[0][i] = 0.f;
    const unsigned sb0 = smem_u32(&hbuf[0][0]);
    const unsigned sb1 = smem_u32(&hbuf[1][0]);
    const unsigned mb0 = smem_u32(&mb[0]);
    const unsigned mb1 = smem_u32(&mb[1]);
    if (threadIdx.x == 0) {
        asm volatile("mbarrier.init.shared.b64 [%0], %1;" :: "r"(mb0), "r"(1u) : "memory");
        asm volatile("mbarrier.init.shared.b64 [%0], %1;" :: "r"(mb1), "r"(1u) : "memory");
        asm volatile("mbarrier.arrive.expect_tx.shared.b64 _, [%0], %1;"
                     :: "r"(mb0), "r"(2048u) : "memory");
        asm volatile("mbarrier.arrive.expect_tx.shared.b64 _, [%0], %1;"
                     :: "r"(mb1), "r"(2048u) : "memory");
    }
    __syncthreads();
    asm volatile("barrier.cluster.arrive.aligned;" ::: "memory");
    asm volatile("barrier.cluster.wait.aligned;" ::: "memory");

    // gi prefetch for step 0
    float giR = 0.f, giZ = 0.f, giN = 0.f;
    {
        const int t0 = dir ? (LL - 1) : 0;
        if (lane < 2) {
            const float* gt = gi + (size_t)t0 * (3 * HH);
            giR = __ldg(gt + myj); giZ = __ldg(gt + HH + myj); giN = __ldg(gt + 2 * HH + myj);
        }
    }

    unsigned par[2] = {0u, 0u};
    for (int s = 0; s < LL; s++) {
        const int t = dir ? (LL - 1 - s) : s;
        // prefetch gi for step s+1 (independent of everything this step)
        float nxR = 0.f, nxZ = 0.f, nxN = 0.f;
        if (s + 1 < LL && lane < 2) {
            const int tn_ = dir ? (LL - 2 - s) : (s + 1);
            const float* gt = gi + (size_t)tn_ * (3 * HH);
            nxR = __ldg(gt + myj); nxZ = __ldg(gt + HH + myj); nxN = __ldg(gt + 2 * HH + myj);
        }
        const int sl = s & 1;
        const unsigned mcur = sl ? mb1 : mb0;
        if (s > 0) {
            mbar_wait(mcur, par[sl]);
            par[sl] ^= 1;
            if (threadIdx.x == 0)
                asm volatile("mbarrier.arrive.expect_tx.shared.b64 _, [%0], %1;"
                             :: "r"(mcur), "r"(2048u) : "memory");
            __syncthreads();
        }
        const float* hp = hbuf[sl];
        ull aR = 0, aZ = 0, aN = 0;
#pragma unroll
        for (int c4 = 0; c4 < 4; c4++) {
            float4 hv = *(const float4*)(hp + lane * 16 + c4 * 4);
            ull h0 = packff(hv.x), h1 = packff(hv.y), h2 = packff(hv.z), h3 = packff(hv.w);
            ffma2(aR, wt[0][c4*4+0], h0); ffma2(aZ, wt[1][c4*4+0], h0); ffma2(aN, wt[2][c4*4+0], h0);
            ffma2(aR, wt[0][c4*4+1], h1); ffma2(aZ, wt[1][c4*4+1], h1); ffma2(aN, wt[2][c4*4+1], h1);
            ffma2(aR, wt[0][c4*4+2], h2); ffma2(aZ, wt[1][c4*4+2], h2); ffma2(aN, wt[2][c4*4+2], h2);
            ffma2(aR, wt[0][c4*4+3], h3); ffma2(aZ, wt[1][c4*4+3], h3); ffma2(aN, wt[2][c4*4+3], h3);
        }
        // packed 64-bit butterfly reduce (both h lanes at once)
#pragma unroll
        for (int o = 16; o; o >>= 1) {
            ull tR = __shfl_xor_sync(0xffffffffu, aR, o);
            ull tZ = __shfl_xor_sync(0xffffffffu, aZ, o);
            ull tN = __shfl_xor_sync(0xffffffffu, aN, o);
            addx2(aR, tR); addx2(aZ, tZ); addx2(aN, tN);
        }
        float2 fR = unpk(aR), fZ = unpk(aZ), fN = unpk(aN);
        float hnew = 0.f;
        if (lane < 2) {
            float aRs = lane ? fR.y : fR.x;
            float aZs = lane ? fZ.y : fZ.x;
            float aNs = lane ? fN.y : fN.x;
            float rr = sigm_(giR + aRs + bR);
            float zz = sigm_(giZ + aZs + bZ);
            float nn = tanh_(giN + rr * (aNs + bN));
            float hprev = hp[myj];
            hnew = (1.f - zz) * nn + zz * hprev;
        }
        // publish h_{s+1}: lanes 0-15 send one packed b64 to rank=lane
        float he = __shfl_sync(0xffffffffu, hnew, 0);
        float ho = __shfl_sync(0xffffffffu, hnew, 1);
        if (s + 1 < LL && lane < 16) {
            ull pairv = pack2(he, ho);
            unsigned ldata = (((s + 1) & 1) ? sb1 : sb0) + (unsigned)j0 * 4u;
            unsigned lmbar = (((s + 1) & 1) ? mb1 : mb0);
            unsigned rdata, rmbar;
            asm("mapa.shared::cluster.u32 %0, %1, %2;" : "=r"(rdata) : "r"(ldata), "r"(lane));
            asm("mapa.shared::cluster.u32 %0, %1, %2;" : "=r"(rmbar) : "r"(lmbar), "r"(lane));
            asm volatile("st.async.shared::cluster.mbarrier::complete_tx::bytes.b64 [%0], %1, [%2];"
                         :: "r"(rdata), "l"(pairv), "r"(rmbar) : "memory");
        }
        if (lane < 2) outp[(size_t)t * (2 * HH) + myj] = hnew;
        giR = nxR; giZ = nxZ; giN = nxN;
    }
    asm volatile("barrier.cluster.arrive.aligned;" ::: "memory");
    asm volatile("barrier.cluster.wait.aligned;" ::: "memory");
}

// ---------------- fallback GRU (R3, global-flag sync) ----------------
__global__ void __launch_bounds__(512, 1) gru_flags(
    const float* __restrict__ whh_f, const float* __restrict__ bhh_f,
    const float* __restrict__ whh_b, const float* __restrict__ bhh_b,
    float* __restrict__ out)
{
    const int dir = blockIdx.x >> 5, cta = blockIdx.x & 31;
    const int wrp = threadIdx.x >> 5, lane = threadIdx.x & 31;
    const int j = cta * 16 + wrp;
    const float* whh = dir ? whh_b : whh_f;
    const float* bhh = dir ? bhh_b : bhh_f;
    const float* gi  = dir ? g_gi_b : g_gi_f;

    float wr[16], wz[16], wn[16];
#pragma unroll
    for (int i = 0; i < 16; i++) {
        int k = lane + 32 * i;
        wr[i] = whh[(size_t)j * HH + k];
        wz[i] = whh[(size_t)(HH + j) * HH + k];
        wn[i] = whh[(size_t)(2 * HH + j) * HH + k];
    }
    const float bhr = bhh[j], bhz = bhh[HH + j], bhn = bhh[2 * HH + j];

    for (int s = 0; s < LL; s++) {
        const int t = dir ? (LL - 1 - s) : s;
        float giR = 0.f, giZ = 0.f, giN = 0.f;
        if (lane == 0) {
            const float* gt = gi + (size_t)t * (3 * HH);
            giR = __ldg(&gt[j]); giZ = __ldg(&gt[HH + j]); giN = __ldg(&gt[2 * HH + j]);
        }
        if (s > 0 && wrp == 0) {
            const unsigned tgt = (unsigned)s;
            while (__any_sync(0xffffffffu, ld_acq(&g_flag[dir][lane][0]) < tgt)) {}
        }
        __syncthreads();
        const float* hp = g_h[dir][s & 1];
        float* hn = g_h[dir][(s + 1) & 1];
        float aR = 0.f, aZ = 0.f, aN = 0.f;
#pragma unroll
        for (int i = 0; i < 16; i++) {
            float hv = __ldcg(&hp[lane + 32 * i]);
            aR = fmaf(wr[i], hv, aR);
            aZ = fmaf(wz[i], hv, aZ);
            aN = fmaf(wn[i], hv, aN);
        }
#pragma unroll
        for (int o = 16; o; o >>= 1) {
            aR += __shfl_xor_sync(0xffffffffu, aR, o);
            aZ += __shfl_xor_sync(0xffffffffu, aZ, o);
            aN += __shfl_xor_sync(0xffffffffu, aN, o);
        }
        if (lane == 0) {
            float r = sigm_(giR + aR + bhr);
            float z = sigm_(giZ + aZ + bhz);
            float n = tanh_(giN + r * (aN + bhn));
            float hprev = __ldcg(&hp[j]);
            float hnew = (1.f - z) * n + z * hprev;
            __stcg(&hn[j], hnew);
            out[(size_t)t * (2 * HH) + dir * HH + j] = hnew;
        }
        __syncthreads();
        if (threadIdx.x == 0) st_rel(&g_flag[dir][cta][0], (unsigned)(s + 1));
    }
}

// ---------------- launch ----------------
extern "C" void kernel_launch(void* const* d_in, const int* in_sizes, int n_in,
                              void* d_out, int out_size) {
    const float* v     = (const float*)d_in[0];
    const float* w1    = (const float*)d_in[1];
    const float* b1    = (const float*)d_in[2];
    const float* w2    = (const float*)d_in[3];
    const float* b2    = (const float*)d_in[4];
    const float* wih_f = (const float*)d_in[5];
    const float* whh_f = (const float*)d_in[6];
    const float* bih_f = (const float*)d_in[7];
    const float* bhh_f = (const float*)d_in[8];
    const float* wih_b = (const float*)d_in[9];
    const float* whh_b = (const float*)d_in[10];
    const float* bih_b = (const float*)d_in[11];
    const float* bhh_b = (const float*)d_in[12];
    float* out = (float*)d_out;

    init_zero<<<2, 1024>>>();
    gemm_uw<<<dim3(8, 8, 2), 256>>>(v, w1, b1, w2, b2);
    attn_e<<<dim3(16, 32), dim3(32, 16)>>>(v);
    softmax_rows<<<512, 512>>>();
    gemm_c<<<dim3(8, 8), 256>>>(v);
    gemm_gi<<<dim3(24, 8, 2), 256>>>(v, wih_f, bih_f, wih_b, bih_b);

    cudaFuncSetAttribute((const void*)gru_cluster,
                         cudaFuncAttributeNonPortableClusterSizeAllowed, 1);
    cudaLaunchConfig_t cfg = {};
    cfg.gridDim = dim3(32, 1, 1);
    cfg.blockDim = dim3(512, 1, 1);
    cfg.dynamicSmemBytes = 0;
    cfg.stream = 0;
    cudaLaunchAttribute attrs[1];
    attrs[0].id = cudaLaunchAttributeClusterDimension;
    attrs[0].val.clusterDim = {16, 1, 1};
    cfg.attrs = attrs;
    cfg.numAttrs = 1;

    int nclus = 0;
    cudaError_t qe = cudaOccupancyMaxActiveClusters(&nclus, gru_cluster, &cfg);
    bool ok = (qe == cudaSuccess && nclus >= 2);
    if (ok) {
        cudaError_t le = cudaLaunchKernelEx(&cfg, gru_cluster,
                                            whh_f, bhh_f, whh_b, bhh_b, out);
        if (le != cudaSuccess) ok = false;
    }
    if (!ok) {
        cudaGetLastError();
        gru_flags<<<64, 512>>>(whh_f, bhh_f, whh_b, bhh_b, out);
    }
}

// round 11
// speedup vs baseline: 3.2576x; 1.0220x over previous
#include <cuda_runtime.h>
#include <cuda_bf16.h>

#define LL 512
#define DD 512
#define HH 512

typedef unsigned long long ull;

// ---------------- device scratch ----------------
__device__ float g_u[LL * DD];
__device__ float g_w[LL * DD];
__device__ float g_e[LL * LL];
__device__ float g_a[LL * LL];
__device__ float g_c[LL * DD];
__device__ float g_gi_f[LL * 3 * HH];
__device__ float g_gi_b[LL * 3 * HH];
__device__ float g_h[2][2][HH];               // fallback: [dir][parity][h]
__device__ unsigned int g_flag[2][32][32];    // fallback: per-producer flag lines

__device__ __forceinline__ float sigm_(float x) {
    return __fdividef(1.f, 1.f + __expf(-x));
}
__device__ __forceinline__ float tanh_(float x) {
    return 1.f - __fdividef(2.f, __expf(x + x) + 1.f);
}
__device__ __forceinline__ unsigned int ld_acq(const unsigned int* p) {
    unsigned int v;
    asm volatile("ld.acquire.gpu.global.u32 %0, [%1];" : "=r"(v) : "l"(p) : "memory");
    return v;
}
__device__ __forceinline__ void st_rel(unsigned int* p, unsigned int v) {
    asm volatile("st.release.gpu.global.u32 [%0], %1;" :: "l"(p), "r"(v) : "memory");
}
__device__ __forceinline__ void ffma2(ull& d, ull a, ull b) {
    asm("fma.rn.f32x2 %0, %1, %2, %0;" : "+l"(d) : "l"(a), "l"(b));
}
__device__ __forceinline__ void addx2(ull& d, ull a) {
    asm("add.rn.f32x2 %0, %0, %1;" : "+l"(d) : "l"(a));
}
__device__ __forceinline__ ull packff(float x) {
    ull r; asm("mov.b64 %0, {%1, %1};" : "=l"(r) : "f"(x)); return r;
}
__device__ __forceinline__ ull pack2(float x, float y) {
    ull r; asm("mov.b64 %0, {%1, %2};" : "=l"(r) : "f"(x), "f"(y)); return r;
}
__device__ __forceinline__ float2 unpk(ull v) {
    float2 f; asm("mov.b64 {%0, %1}, %2;" : "=f"(f.x), "=f"(f.y) : "l"(v)); return f;
}
__device__ __forceinline__ unsigned smem_u32(const void* p) {
    unsigned a;
    asm("{ .reg .u64 t; cvta.to.shared.u64 t, %1; cvt.u32.u64 %0, t; }" : "=r"(a) : "l"(p));
    return a;
}
__device__ __forceinline__ unsigned ctarank_() {
    unsigned r; asm("mov.u32 %0, %%cluster_ctarank;" : "=r"(r)); return r;
}
__device__ __forceinline__ void mbar_wait(unsigned addr, unsigned parity) {
    asm volatile(
        "{\n\t"
        ".reg .pred P;\n\t"
        "WL_%=:\n\t"
        "mbarrier.try_wait.parity.acquire.cta.shared::cta.b64 P, [%0], %1, 0x989680;\n\t"
        "@!P bra WL_%=;\n\t"
        "}"
        :: "r"(addr), "r"(parity) : "memory");
}

// ---------------- init (zero fallback h + flags) ----------------
__global__ void init_zero() {
    int i = blockIdx.x * 1024 + threadIdx.x;
    if (i < 2048) ((unsigned int*)g_flag)[i] = 0u;
    if (i < 2048) ((float*)g_h)[i] = 0.f;
}

// ---------------- GEMM core (f32x2 packed, lda/ldb/accum generalized) ----------------
// C[M,N](+)= A[M,Kloop](lda) * op(B) + bias
// transB=1: B rows are N, stride ldb. transB=0: B is [Kloop,N] stride ldb.
__device__ __forceinline__ void gemm_core(
    const float* __restrict__ A, int lda,
    const float* __restrict__ B, int ldb,
    const float* __restrict__ bias, float* __restrict__ C,
    int N, int Kloop, int transB, int accum)
{
    __shared__ __align__(16) float As[16][68];
    __shared__ __align__(16) float Bs[16][68];
    const int tid = threadIdx.x;
    const int m0 = blockIdx.y * 64, n0 = blockIdx.x * 64;
    const int tm = (tid >> 4) * 4, tn = (tid & 15) * 4;
    ull acc[4][2] = {};
    for (int k0 = 0; k0 < Kloop; k0 += 16) {
#pragma unroll
        for (int i = 0; i < 4; i++) {
            int e = tid + 256 * i;
            {
                int kk = e & 15, row = e >> 4;
                As[kk][row] = A[(size_t)(m0 + row) * lda + k0 + kk];
            }
            if (transB) {
                int kk = e & 15, row = e >> 4;
                Bs[kk][row] = B[(size_t)(n0 + row) * ldb + k0 + kk];
            } else {
                int n = e & 63, kk = e >> 6;
                Bs[kk][n] = B[(size_t)(k0 + kk) * ldb + n0 + n];
            }
        }
        __syncthreads();
#pragma unroll
        for (int kk = 0; kk < 16; kk++) {
            float4 a = *(const float4*)&As[kk][tm];
            const ull* bp = (const ull*)&Bs[kk][tn];
            ull b01 = bp[0], b23 = bp[1];
            ull a0 = packff(a.x), a1 = packff(a.y), a2 = packff(a.z), a3 = packff(a.w);
            ffma2(acc[0][0], a0, b01); ffma2(acc[0][1], a0, b23);
            ffma2(acc[1][0], a1, b01); ffma2(acc[1][1], a1, b23);
            ffma2(acc[2][0], a2, b01); ffma2(acc[2][1], a2, b23);
            ffma2(acc[3][0], a3, b01); ffma2(acc[3][1], a3, b23);
        }
        __syncthreads();
    }
#pragma unroll
    for (int i = 0; i < 4; i++) {
        float2 c01 = unpk(acc[i][0]), c23 = unpk(acc[i][1]);
        float* cp = C + (size_t)(m0 + tm + i) * N + n0 + tn;
        float b0 = 0.f, b1 = 0.f, b2 = 0.f, b3 = 0.f;
        if (bias) { b0 = bias[n0+tn]; b1 = bias[n0+tn+1]; b2 = bias[n0+tn+2]; b3 = bias[n0+tn+3]; }
        if (accum) { b0 += cp[0]; b1 += cp[1]; b2 += cp[2]; b3 += cp[3]; }
        cp[0] = c01.x + b0; cp[1] = c01.y + b1; cp[2] = c23.x + b2; cp[3] = c23.y + b3;
    }
}

// head: z=0 -> u, z=1 -> w (8x8 blocks), z=2 -> gi_f v-half, z=3 -> gi_b v-half (24x8)
__global__ void gemm_head(const float* __restrict__ v,
                          const float* __restrict__ w1, const float* __restrict__ b1,
                          const float* __restrict__ w2, const float* __restrict__ b2,
                          const float* __restrict__ wih_f, const float* __restrict__ bih_f,
                          const float* __restrict__ wih_b, const float* __restrict__ bih_b) {
    const int z = blockIdx.z;
    if (z < 2) {
        if (blockIdx.x >= 8) return;
        if (z == 0) gemm_core(v, 512, w1, 512, b1, g_u, 512, 512, 1, 0);
        else        gemm_core(v, 512, w2, 512, b2, g_w, 512, 512, 1, 0);
    } else {
        if (z == 2) gemm_core(v, 512, wih_f, 1024, bih_f, g_gi_f, 1536, 512, 1, 0);
        else        gemm_core(v, 512, wih_b, 1024, bih_b, g_gi_b, 1536, 512, 1, 0);
    }
}
__global__ void gemm_c(const float* __restrict__ v) {
    gemm_core(g_a, 512, v, 512, nullptr, g_c, 512, 512, 0, 0);
}
// tail: gi += c @ wih[:, 512:]^T
__global__ void gemm_tail(const float* __restrict__ wih_f, const float* __restrict__ wih_b) {
    if (blockIdx.z == 0) gemm_core(g_c, 512, wih_f + 512, 1024, nullptr, g_gi_f, 1536, 512, 1, 1);
    else                 gemm_core(g_c, 512, wih_b + 512, 1024, nullptr, g_gi_b, 1536, 512, 1, 1);
}

// ---------------- attn e ----------------
__global__ void attn_e(const float* __restrict__ v) {
    __shared__ float us[32][33], vs[32][33], ws[16][33];
    const int tx = threadIdx.x, ty = threadIdx.y;
    const int j0 = blockIdx.x * 32, t0 = blockIdx.y * 16;
    float acc = 0.f;
    for (int d0 = 0; d0 < DD; d0 += 32) {
        us[ty][tx]      = g_u[(j0 + ty) * DD + d0 + tx];
        us[ty + 16][tx] = g_u[(j0 + ty + 16) * DD + d0 + tx];
        vs[ty][tx]      = v[(j0 + ty) * DD + d0 + tx];
        vs[ty + 16][tx] = v[(j0 + ty + 16) * DD + d0 + tx];
        ws[ty][tx]      = g_w[(t0 + ty) * DD + d0 + tx];
        __syncthreads();
#pragma unroll
        for (int dd = 0; dd < 32; dd++) {
            float x = us[tx][dd] + ws[ty][dd];
            float th = 1.f - __fdividef(2.f, __expf(x + x) + 1.f);
            acc = fmaf(th, vs[tx][dd], acc);
        }
        __syncthreads();
    }
    g_e[(t0 + ty) * LL + j0 + tx] = acc;
}

// ---------------- softmax rows ----------------
__global__ void softmax_rows() {
    __shared__ float red[16];
    __shared__ float bval;
    const int t = blockIdx.x, tid = threadIdx.x, w = tid >> 5, l = tid & 31;
    float x = g_e[t * LL + tid];
    float m = x;
#pragma unroll
    for (int o = 16; o; o >>= 1) m = fmaxf(m, __shfl_xor_sync(~0u, m, o));
    if (l == 0) red[w] = m;
    __syncthreads();
    if (tid == 0) {
        float mm = red[0];
#pragma unroll
        for (int i = 1; i < 16; i++) mm = fmaxf(mm, red[i]);
        bval = mm;
    }
    __syncthreads();
    float p = __expf(x - bval);
    float s = p;
#pragma unroll
    for (int o = 16; o; o >>= 1) s += __shfl_xor_sync(~0u, s, o);
    if (l == 0) red[w] = s;
    __syncthreads();
    if (tid == 0) {
        float ss = red[0];
#pragma unroll
        for (int i = 1; i < 16; i++) ss += red[i];
        bval = ss;
    }
    __syncthreads();
    g_a[t * LL + tid] = __fdividef(p, bval);
}

// ======== GRU scan: 16-CTA cluster, b64 st.async publish, no per-step BAR ========
__global__ void __launch_bounds__(512, 1) gru_cluster(
    const float* __restrict__ whh_f, const float* __restrict__ bhh_f,
    const float* __restrict__ whh_b, const float* __restrict__ bhh_b,
    float* __restrict__ out)
{
    __shared__ __align__(16) float hbuf[2][HH];
    __shared__ __align__(8) ull mb[2];
    const int dir = blockIdx.x >> 4;
    const int wrp = threadIdx.x >> 5, lane = threadIdx.x & 31;
    const unsigned rank = ctarank_();
    const int j0 = (int)rank * 32 + wrp * 2;
    const int myj = j0 + (lane & 1);
    const float* whh = dir ? whh_b : whh_f;
    const float* bhh = dir ? bhh_b : bhh_f;
    const float* gi  = dir ? g_gi_b : g_gi_f;
    float* outp = out + dir * HH;

    ull wt[3][16];
#pragma unroll
    for (int g = 0; g < 3; g++) {
        const float* r0 = whh + ((size_t)(g * HH + j0)) * HH + lane * 16;
        const float* r1 = r0 + HH;
#pragma unroll
        for (int c = 0; c < 16; c++) wt[g][c] = pack2(r0[c], r1[c]);
    }
    const float bR = bhh[myj], bZ = bhh[HH + myj], bN = bhh[2 * HH + myj];

    for (int i = threadIdx.x; i < HH; i += 512) hbuf[0][i] = 0.f;
    const unsigned sb0 = smem_u32(&hbuf[0][0]);
    const unsigned sb1 = smem_u32(&hbuf[1][0]);
    const unsigned mb0 = smem_u32(&mb[0]);
    const unsigned mb1 = smem_u32(&mb[1]);
    if (threadIdx.x == 0) {
        asm volatile("mbarrier.init.shared.b64 [%0], %1;" :: "r"(mb0), "r"(1u) : "memory");
        asm volatile("mbarrier.init.shared.b64 [%0], %1;" :: "r"(mb1), "r"(1u) : "memory");
        asm volatile("mbarrier.arrive.expect_tx.shared.b64 _, [%0], %1;"
                     :: "r"(mb0), "r"(2048u) : "memory");
        asm volatile("mbarrier.arrive.expect_tx.shared.b64 _, [%0], %1;"
                     :: "r"(mb1), "r"(2048u) : "memory");
    }
    __syncthreads();
    asm volatile("barrier.cluster.arrive.aligned;" ::: "memory");
    asm volatile("barrier.cluster.wait.aligned;" ::: "memory");

    // gi prefetch for step 0
    float giR = 0.f, giZ = 0.f, giN = 0.f;
    {
        const int t0 = dir ? (LL - 1) : 0;
        if (lane < 2) {
            const float* gt = gi + (size_t)t0 * (3 * HH);
            giR = __ldg(gt + myj); giZ = __ldg(gt + HH + myj); giN = __ldg(gt + 2 * HH + myj);
        }
    }

    unsigned par[2] = {0u, 0u};
    for (int s = 0; s < LL; s++) {
        const int t = dir ? (LL - 1 - s) : s;
        // prefetch gi for step s+1
        float nxR = 0.f, nxZ = 0.f, nxN = 0.f;
        if (s + 1 < LL && lane < 2) {
            const int tn_ = dir ? (LL - 2 - s) : (s + 1);
            const float* gt = gi + (size_t)tn_ * (3 * HH);
            nxR = __ldg(gt + myj); nxZ = __ldg(gt + HH + myj); nxN = __ldg(gt + 2 * HH + myj);
        }
        const int sl = s & 1;
        const unsigned mcur = sl ? mb1 : mb0;
        if (s > 0) {
            mbar_wait(mcur, par[sl]);
            par[sl] ^= 1;
            // re-arm for h_{s+2}; safety: warp0's own publish (below) is ordered
            // after this, and all remote h_{s+2} sends are gated on warp0's h_{s+1}.
            if (threadIdx.x == 0)
                asm volatile("mbarrier.arrive.expect_tx.shared.b64 _, [%0], %1;"
                             :: "r"(mcur), "r"(2048u) : "memory");
            // NO __syncthreads: warps proceed independently.
        }
        const float* hp = hbuf[sl];
        ull aR = 0, aZ = 0, aN = 0;
#pragma unroll
        for (int c4 = 0; c4 < 4; c4++) {
            float4 hv = *(const float4*)(hp + lane * 16 + c4 * 4);
            ull h0 = packff(hv.x), h1 = packff(hv.y), h2 = packff(hv.z), h3 = packff(hv.w);
            ffma2(aR, wt[0][c4*4+0], h0); ffma2(aZ, wt[1][c4*4+0], h0); ffma2(aN, wt[2][c4*4+0], h0);
            ffma2(aR, wt[0][c4*4+1], h1); ffma2(aZ, wt[1][c4*4+1], h1); ffma2(aN, wt[2][c4*4+1], h1);
            ffma2(aR, wt[0][c4*4+2], h2); ffma2(aZ, wt[1][c4*4+2], h2); ffma2(aN, wt[2][c4*4+2], h2);
            ffma2(aR, wt[0][c4*4+3], h3); ffma2(aZ, wt[1][c4*4+3], h3); ffma2(aN, wt[2][c4*4+3], h3);
        }
#pragma unroll
        for (int o = 16; o; o >>= 1) {
            ull tR = __shfl_xor_sync(0xffffffffu, aR, o);
            ull tZ = __shfl_xor_sync(0xffffffffu, aZ, o);
            ull tN = __shfl_xor_sync(0xffffffffu, aN, o);
            addx2(aR, tR); addx2(aZ, tZ); addx2(aN, tN);
        }
        float2 fR = unpk(aR), fZ = unpk(aZ), fN = unpk(aN);
        float hnew = 0.f;
        if (lane < 2) {
            float aRs = lane ? fR.y : fR.x;
            float aZs = lane ? fZ.y : fZ.x;
            float aNs = lane ? fN.y : fN.x;
            float rr = sigm_(giR + aRs + bR);
            float zz = sigm_(giZ + aZs + bZ);
            float nn = tanh_(giN + rr * (aNs + bN));
            float hprev = hp[myj];
            hnew = (1.f - zz) * nn + zz * hprev;
        }
        float he = __shfl_sync(0xffffffffu, hnew, 0);
        float ho = __shfl_sync(0xffffffffu, hnew, 1);
        if (s + 1 < LL && lane < 16) {
            ull pairv = pack2(he, ho);
            unsigned ldata = (((s + 1) & 1) ? sb1 : sb0) + (unsigned)j0 * 4u;
            unsigned lmbar = (((s + 1) & 1) ? mb1 : mb0);
            unsigned rdata, rmbar;
            asm("mapa.shared::cluster.u32 %0, %1, %2;" : "=r"(rdata) : "r"(ldata), "r"(lane));
            asm("mapa.shared::cluster.u32 %0, %1, %2;" : "=r"(rmbar) : "r"(lmbar), "r"(lane));
            asm volatile("st.async.shared::cluster.mbarrier::complete_tx::bytes.b64 [%0], %1, [%2];"
                         :: "r"(rdata), "l"(pairv), "r"(rmbar) : "memory");
        }
        if (lane < 2) outp[(size_t)t * (2 * HH) + myj] = hnew;
        giR = nxR; giZ = nxZ; giN = nxN;
    }
    asm volatile("barrier.cluster.arrive.aligned;" ::: "memory");
    asm volatile("barrier.cluster.wait.aligned;" ::: "memory");
}

// ---------------- fallback GRU (R3, global-flag sync) ----------------
__global__ void __launch_bounds__(512, 1) gru_flags(
    const float* __restrict__ whh_f, const float* __restrict__ bhh_f,
    const float* __restrict__ whh_b, const float* __restrict__ bhh_b,
    float* __restrict__ out)
{
    const int dir = blockIdx.x >> 5, cta = blockIdx.x & 31;
    const int wrp = threadIdx.x >> 5, lane = threadIdx.x & 31;
    const int j = cta * 16 + wrp;
    const float* whh = dir ? whh_b : whh_f;
    const float* bhh = dir ? bhh_b : bhh_f;
    const float* gi  = dir ? g_gi_b : g_gi_f;

    float wr[16], wz[16], wn[16];
#pragma unroll
    for (int i = 0; i < 16; i++) {
        int k = lane + 32 * i;
        wr[i] = whh[(size_t)j * HH + k];
        wz[i] = whh[(size_t)(HH + j) * HH + k];
        wn[i] = whh[(size_t)(2 * HH + j) * HH + k];
    }
    const float bhr = bhh[j], bhz = bhh[HH + j], bhn = bhh[2 * HH + j];

    for (int s = 0; s < LL; s++) {
        const int t = dir ? (LL - 1 - s) : s;
        float giR = 0.f, giZ = 0.f, giN = 0.f;
        if (lane == 0) {
            const float* gt = gi + (size_t)t * (3 * HH);
            giR = __ldg(&gt[j]); giZ = __ldg(&gt[HH + j]); giN = __ldg(&gt[2 * HH + j]);
        }
        if (s > 0 && wrp == 0) {
            const unsigned tgt = (unsigned)s;
            while (__any_sync(0xffffffffu, ld_acq(&g_flag[dir][lane][0]) < tgt)) {}
        }
        __syncthreads();
        const float* hp = g_h[dir][s & 1];
        float* hn = g_h[dir][(s + 1) & 1];
        float aR = 0.f, aZ = 0.f, aN = 0.f;
#pragma unroll
        for (int i = 0; i < 16; i++) {
            float hv = __ldcg(&hp[lane + 32 * i]);
            aR = fmaf(wr[i], hv, aR);
            aZ = fmaf(wz[i], hv, aZ);
            aN = fmaf(wn[i], hv, aN);
        }
#pragma unroll
        for (int o = 16; o; o >>= 1) {
            aR += __shfl_xor_sync(0xffffffffu, aR, o);
            aZ += __shfl_xor_sync(0xffffffffu, aZ, o);
            aN += __shfl_xor_sync(0xffffffffu, aN, o);
        }
        if (lane == 0) {
            float r = sigm_(giR + aR + bhr);
            float z = sigm_(giZ + aZ + bhz);
            float n = tanh_(giN + r * (aN + bhn));
            float hprev = __ldcg(&hp[j]);
            float hnew = (1.f - z) * n + z * hprev;
            __stcg(&hn[j], hnew);
            out[(size_t)t * (2 * HH) + dir * HH + j] = hnew;
        }
        __syncthreads();
        if (threadIdx.x == 0) st_rel(&g_flag[dir][cta][0], (unsigned)(s + 1));
    }
}

// ---------------- launch ----------------
extern "C" void kernel_launch(void* const* d_in, const int* in_sizes, int n_in,
                              void* d_out, int out_size) {
    const float* v     = (const float*)d_in[0];
    const float* w1    = (const float*)d_in[1];
    const float* b1    = (const float*)d_in[2];
    const float* w2    = (const float*)d_in[3];
    const float* b2    = (const float*)d_in[4];
    const float* wih_f = (const float*)d_in[5];
    const float* whh_f = (const float*)d_in[6];
    const float* bih_f = (const float*)d_in[7];
    const float* bhh_f = (const float*)d_in[8];
    const float* wih_b = (const float*)d_in[9];
    const float* whh_b = (const float*)d_in[10];
    const float* bih_b = (const float*)d_in[11];
    const float* bhh_b = (const float*)d_in[12];
    float* out = (float*)d_out;

    init_zero<<<2, 1024>>>();
    // u, w, and the v-half of both gi GEMMs run concurrently in one launch
    gemm_head<<<dim3(24, 8, 4), 256>>>(v, w1, b1, w2, b2,
                                       wih_f, bih_f, wih_b, bih_b);
    attn_e<<<dim3(16, 32), dim3(32, 16)>>>(v);
    softmax_rows<<<512, 512>>>();
    gemm_c<<<dim3(8, 8), 256>>>(v);
    gemm_tail<<<dim3(24, 8, 2), 256>>>(wih_f, wih_b);

    cudaFuncSetAttribute((const void*)gru_cluster,
                         cudaFuncAttributeNonPortableClusterSizeAllowed, 1);
    cudaLaunchConfig_t cfg = {};
    cfg.gridDim = dim3(32, 1, 1);
    cfg.blockDim = dim3(512, 1, 1);
    cfg.dynamicSmemBytes = 0;
    cfg.stream = 0;
    cudaLaunchAttribute attrs[1];
    attrs[0].id = cudaLaunchAttributeClusterDimension;
    attrs[0].val.clusterDim = {16, 1, 1};
    cfg.attrs = attrs;
    cfg.numAttrs = 1;

    int nclus = 0;
    cudaError_t qe = cudaOccupancyMaxActiveClusters(&nclus, gru_cluster, &cfg);
    bool ok = (qe == cudaSuccess && nclus >= 2);
    if (ok) {
        cudaError_t le = cudaLaunchKernelEx(&cfg, gru_cluster,
                                            whh_f, bhh_f, whh_b, bhh_b, out);
        if (le != cudaSuccess) ok = false;
    }
    if (!ok) {
        cudaGetLastError();
        gru_flags<<<64, 512>>>(whh_f, bhh_f, whh_b, bhh_b, out);
    }
}

// round 12
// speedup vs baseline: 4.0729x; 1.2503x over previous
#include <cuda_runtime.h>
#include <cuda_bf16.h>

#define LL 512
#define DD 512
#define HH 512

typedef unsigned long long ull;

// ---------------- device scratch ----------------
__device__ float g_u[LL * DD];
__device__ float g_w[LL * DD];
__device__ float g_e[LL * LL];
__device__ float g_a[LL * LL];
__device__ float g_c[LL * DD];
__device__ float g_gi_f[LL * 3 * HH];
__device__ float g_gi_b[LL * 3 * HH];
__device__ float g_h[2][2][HH];               // fallback: [dir][parity][h]
__device__ unsigned int g_flag[2][32][32];    // fallback: per-producer flag lines

__device__ __forceinline__ float sigm_(float x) {
    return __fdividef(1.f, 1.f + __expf(-x));
}
__device__ __forceinline__ float tanh_(float x) {
    return 1.f - __fdividef(2.f, __expf(x + x) + 1.f);
}
__device__ __forceinline__ unsigned int ld_acq(const unsigned int* p) {
    unsigned int v;
    asm volatile("ld.acquire.gpu.global.u32 %0, [%1];" : "=r"(v) : "l"(p) : "memory");
    return v;
}
__device__ __forceinline__ void st_rel(unsigned int* p, unsigned int v) {
    asm volatile("st.release.gpu.global.u32 [%0], %1;" :: "l"(p), "r"(v) : "memory");
}
__device__ __forceinline__ void ffma2(ull& d, ull a, ull b) {
    asm("fma.rn.f32x2 %0, %1, %2, %0;" : "+l"(d) : "l"(a), "l"(b));
}
__device__ __forceinline__ void addx2(ull& d, ull a) {
    asm("add.rn.f32x2 %0, %0, %1;" : "+l"(d) : "l"(a));
}
__device__ __forceinline__ ull packff(float x) {
    ull r; asm("mov.b64 %0, {%1, %1};" : "=l"(r) : "f"(x)); return r;
}
__device__ __forceinline__ ull pack2(float x, float y) {
    ull r; asm("mov.b64 %0, {%1, %2};" : "=l"(r) : "f"(x), "f"(y)); return r;
}
__device__ __forceinline__ float2 unpk(ull v) {
    float2 f; asm("mov.b64 {%0, %1}, %2;" : "=f"(f.x), "=f"(f.y) : "l"(v)); return f;
}
__device__ __forceinline__ unsigned smem_u32(const void* p) {
    unsigned a;
    asm("{ .reg .u64 t; cvta.to.shared.u64 t, %1; cvt.u32.u64 %0, t; }" : "=r"(a) : "l"(p));
    return a;
}
__device__ __forceinline__ unsigned ctarank_() {
    unsigned r; asm("mov.u32 %0, %%cluster_ctarank;" : "=r"(r)); return r;
}
__device__ __forceinline__ void mbar_wait(unsigned addr, unsigned parity) {
    asm volatile(
        "{\n\t"
        ".reg .pred P;\n\t"
        "WL_%=:\n\t"
        "mbarrier.try_wait.parity.acquire.cta.shared::cta.b64 P, [%0], %1, 0x989680;\n\t"
        "@!P bra WL_%=;\n\t"
        "}"
        :: "r"(addr), "r"(parity) : "memory");
}
__device__ __forceinline__ void mbar_rearm(unsigned addr, unsigned bytes) {
    asm volatile("mbarrier.arrive.expect_tx.shared.b64 _, [%0], %1;"
                 :: "r"(addr), "r"(bytes) : "memory");
}

// ---------------- init (fallback path only) ----------------
__global__ void init_zero() {
    int i = blockIdx.x * 1024 + threadIdx.x;
    if (i < 2048) ((unsigned int*)g_flag)[i] = 0u;
    if (i < 2048) ((float*)g_h)[i] = 0.f;
}

// ---------------- GEMM core (f32x2 packed, lda/ldb/accum generalized) ----------------
__device__ __forceinline__ void gemm_core(
    const float* __restrict__ A, int lda,
    const float* __restrict__ B, int ldb,
    const float* __restrict__ bias, float* __restrict__ C,
    int N, int Kloop, int transB, int accum)
{
    __shared__ __align__(16) float As[16][68];
    __shared__ __align__(16) float Bs[16][68];
    const int tid = threadIdx.x;
    const int m0 = blockIdx.y * 64, n0 = blockIdx.x * 64;
    const int tm = (tid >> 4) * 4, tn = (tid & 15) * 4;
    ull acc[4][2] = {};
    for (int k0 = 0; k0 < Kloop; k0 += 16) {
#pragma unroll
        for (int i = 0; i < 4; i++) {
            int e = tid + 256 * i;
            {
                int kk = e & 15, row = e >> 4;
                As[kk][row] = A[(size_t)(m0 + row) * lda + k0 + kk];
            }
            if (transB) {
                int kk = e & 15, row = e >> 4;
                Bs[kk][row] = B[(size_t)(n0 + row) * ldb + k0 + kk];
            } else {
                int n = e & 63, kk = e >> 6;
                Bs[kk][n] = B[(size_t)(k0 + kk) * ldb + n0 + n];
            }
        }
        __syncthreads();
#pragma unroll
        for (int kk = 0; kk < 16; kk++) {
            float4 a = *(const float4*)&As[kk][tm];
            const ull* bp = (const ull*)&Bs[kk][tn];
            ull b01 = bp[0], b23 = bp[1];
            ull a0 = packff(a.x), a1 = packff(a.y), a2 = packff(a.z), a3 = packff(a.w);
            ffma2(acc[0][0], a0, b01); ffma2(acc[0][1], a0, b23);
            ffma2(acc[1][0], a1, b01); ffma2(acc[1][1], a1, b23);
            ffma2(acc[2][0], a2, b01); ffma2(acc[2][1], a2, b23);
            ffma2(acc[3][0], a3, b01); ffma2(acc[3][1], a3, b23);
        }
        __syncthreads();
    }
#pragma unroll
    for (int i = 0; i < 4; i++) {
        float2 c01 = unpk(acc[i][0]), c23 = unpk(acc[i][1]);
        float* cp = C + (size_t)(m0 + tm + i) * N + n0 + tn;
        float b0 = 0.f, b1 = 0.f, b2 = 0.f, b3 = 0.f;
        if (bias) { b0 = bias[n0+tn]; b1 = bias[n0+tn+1]; b2 = bias[n0+tn+2]; b3 = bias[n0+tn+3]; }
        if (accum) { b0 += cp[0]; b1 += cp[1]; b2 += cp[2]; b3 += cp[3]; }
        cp[0] = c01.x + b0; cp[1] = c01.y + b1; cp[2] = c23.x + b2; cp[3] = c23.y + b3;
    }
}

// head: z=0 -> u, z=1 -> w (8x8 blocks), z=2 -> gi_f v-half, z=3 -> gi_b v-half (24x8)
__global__ void gemm_head(const float* __restrict__ v,
                          const float* __restrict__ w1, const float* __restrict__ b1,
                          const float* __restrict__ w2, const float* __restrict__ b2,
                          const float* __restrict__ wih_f, const float* __restrict__ bih_f,
                          const float* __restrict__ wih_b, const float* __restrict__ bih_b) {
    const int z = blockIdx.z;
    if (z < 2) {
        if (blockIdx.x >= 8) return;
        if (z == 0) gemm_core(v, 512, w1, 512, b1, g_u, 512, 512, 1, 0);
        else        gemm_core(v, 512, w2, 512, b2, g_w, 512, 512, 1, 0);
    } else {
        if (z == 2) gemm_core(v, 512, wih_f, 1024, bih_f, g_gi_f, 1536, 512, 1, 0);
        else        gemm_core(v, 512, wih_b, 1024, bih_b, g_gi_b, 1536, 512, 1, 0);
    }
}
__global__ void gemm_c(const float* __restrict__ v) {
    gemm_core(g_a, 512, v, 512, nullptr, g_c, 512, 512, 0, 0);
}
__global__ void gemm_tail(const float* __restrict__ wih_f, const float* __restrict__ wih_b) {
    if (blockIdx.z == 0) gemm_core(g_c, 512, wih_f + 512, 1024, nullptr, g_gi_f, 1536, 512, 1, 1);
    else                 gemm_core(g_c, 512, wih_b + 512, 1024, nullptr, g_gi_b, 1536, 512, 1, 1);
}

// ---------------- attn e ----------------
__global__ void attn_e(const float* __restrict__ v) {
    __shared__ float us[32][33], vs[32][33], ws[16][33];
    const int tx = threadIdx.x, ty = threadIdx.y;
    const int j0 = blockIdx.x * 32, t0 = blockIdx.y * 16;
    float acc = 0.f;
    for (int d0 = 0; d0 < DD; d0 += 32) {
        us[ty][tx]      = g_u[(j0 + ty) * DD + d0 + tx];
        us[ty + 16][tx] = g_u[(j0 + ty + 16) * DD + d0 + tx];
        vs[ty][tx]      = v[(j0 + ty) * DD + d0 + tx];
        vs[ty + 16][tx] = v[(j0 + ty + 16) * DD + d0 + tx];
        ws[ty][tx]      = g_w[(t0 + ty) * DD + d0 + tx];
        __syncthreads();
#pragma unroll
        for (int dd = 0; dd < 32; dd++) {
            float x = us[tx][dd] + ws[ty][dd];
            float th = 1.f - __fdividef(2.f, __expf(x + x) + 1.f);
            acc = fmaf(th, vs[tx][dd], acc);
        }
        __syncthreads();
    }
    g_e[(t0 + ty) * LL + j0 + tx] = acc;
}

// ---------------- softmax rows ----------------
__global__ void softmax_rows() {
    __shared__ float red[16];
    __shared__ float bval;
    const int t = blockIdx.x, tid = threadIdx.x, w = tid >> 5, l = tid & 31;
    float x = g_e[t * LL + tid];
    float m = x;
#pragma unroll
    for (int o = 16; o; o >>= 1) m = fmaxf(m, __shfl_xor_sync(~0u, m, o));
    if (l == 0) red[w] = m;
    __syncthreads();
    if (tid == 0) {
        float mm = red[0];
#pragma unroll
        for (int i = 1; i < 16; i++) mm = fmaxf(mm, red[i]);
        bval = mm;
    }
    __syncthreads();
    float p = __expf(x - bval);
    float s = p;
#pragma unroll
    for (int o = 16; o; o >>= 1) s += __shfl_xor_sync(~0u, s, o);
    if (l == 0) red[w] = s;
    __syncthreads();
    if (tid == 0) {
        float ss = red[0];
#pragma unroll
        for (int i = 1; i < 16; i++) ss += red[i];
        bval = ss;
    }
    __syncthreads();
    g_a[t * LL + tid] = __fdividef(p, bval);
}

// ======== GRU scan: 16-CTA cluster, chunked st.async publish (2 chunk mbarriers) ========
// h layout for matvec: thread covers k = lane + 32*i  (iteration i consumes source
// rank i's data). Chunk A = ranks 0-7, chunk B = ranks 8-15; per-chunk mbarriers
// let the first half of the matvec overlap the tail of arrivals.
__global__ void __launch_bounds__(512, 1) gru_cluster(
    const float* __restrict__ whh_f, const float* __restrict__ bhh_f,
    const float* __restrict__ whh_b, const float* __restrict__ bhh_b,
    float* __restrict__ out)
{
    __shared__ __align__(16) float hbuf[2][HH];
    __shared__ __align__(8) ull mbA[2], mbB[2];
    const int dir = blockIdx.x >> 4;
    const int wrp = threadIdx.x >> 5, lane = threadIdx.x & 31;
    const unsigned rank = ctarank_();
    const int j0 = (int)rank * 32 + wrp * 2;
    const int myj = j0 + (lane & 1);
    const float* whh = dir ? whh_b : whh_f;
    const float* bhh = dir ? bhh_b : bhh_f;
    const float* gi  = dir ? g_gi_b : g_gi_f;
    float* outp = out + dir * HH;

    // weights packed for k = lane + 32*i
    ull wt[3][16];
#pragma unroll
    for (int g = 0; g < 3; g++) {
        const float* r0 = whh + ((size_t)(g * HH + j0)) * HH;
        const float* r1 = r0 + HH;
#pragma unroll
        for (int i = 0; i < 16; i++) {
            int k = lane + 32 * i;
            wt[g][i] = pack2(r0[k], r1[k]);
        }
    }
    const float bR = bhh[myj], bZ = bhh[HH + myj], bN = bhh[2 * HH + myj];

    for (int i = threadIdx.x; i < HH; i += 512) hbuf[0][i] = 0.f;
    const unsigned sb0 = smem_u32(&hbuf[0][0]);
    const unsigned sb1 = smem_u32(&hbuf[1][0]);
    const unsigned mA0 = smem_u32(&mbA[0]), mA1 = smem_u32(&mbA[1]);
    const unsigned mB0 = smem_u32(&mbB[0]), mB1 = smem_u32(&mbB[1]);
    if (threadIdx.x == 0) {
        asm volatile("mbarrier.init.shared.b64 [%0], %1;" :: "r"(mA0), "r"(1u) : "memory");
        asm volatile("mbarrier.init.shared.b64 [%0], %1;" :: "r"(mA1), "r"(1u) : "memory");
        asm volatile("mbarrier.init.shared.b64 [%0], %1;" :: "r"(mB0), "r"(1u) : "memory");
        asm volatile("mbarrier.init.shared.b64 [%0], %1;" :: "r"(mB1), "r"(1u) : "memory");
        mbar_rearm(mA0, 1024u); mbar_rearm(mA1, 1024u);
        mbar_rearm(mB0, 1024u); mbar_rearm(mB1, 1024u);
    }
    __syncthreads();
    asm volatile("barrier.cluster.arrive.aligned;" ::: "memory");
    asm volatile("barrier.cluster.wait.aligned;" ::: "memory");

    // gi prefetch for step 0
    float giR = 0.f, giZ = 0.f, giN = 0.f;
    {
        const int t0 = dir ? (LL - 1) : 0;
        if (lane < 2) {
            const float* gt = gi + (size_t)t0 * (3 * HH);
            giR = __ldg(gt + myj); giZ = __ldg(gt + HH + myj); giN = __ldg(gt + 2 * HH + myj);
        }
    }

    unsigned parA[2] = {0u, 0u}, parB[2] = {0u, 0u};
    for (int s = 0; s < LL; s++) {
        const int t = dir ? (LL - 1 - s) : s;
        // prefetch gi for step s+1
        float nxR = 0.f, nxZ = 0.f, nxN = 0.f;
        if (s + 1 < LL && lane < 2) {
            const int tn_ = dir ? (LL - 2 - s) : (s + 1);
            const float* gt = gi + (size_t)tn_ * (3 * HH);
            nxR = __ldg(gt + myj); nxZ = __ldg(gt + HH + myj); nxN = __ldg(gt + 2 * HH + myj);
        }
        const int sl = s & 1;
        const float* hp = hbuf[sl];
        ull aR = 0, aZ = 0, aN = 0;

        // ---- chunk A: source ranks 0-7 (h[0..255]) ----
        if (s > 0) {
            const unsigned mA = sl ? mA1 : mA0;
            mbar_wait(mA, parA[sl]); parA[sl] ^= 1;
            if (threadIdx.x == 0) mbar_rearm(mA, 1024u);
        }
#pragma unroll
        for (int i = 0; i < 8; i++) {
            ull hh = packff(hp[lane + 32 * i]);
            ffma2(aR, wt[0][i], hh); ffma2(aZ, wt[1][i], hh); ffma2(aN, wt[2][i], hh);
        }
        // ---- chunk B: source ranks 8-15 (h[256..511]) ----
        if (s > 0) {
            const unsigned mB = sl ? mB1 : mB0;
            mbar_wait(mB, parB[sl]); parB[sl] ^= 1;
            if (threadIdx.x == 0) mbar_rearm(mB, 1024u);
        }
#pragma unroll
        for (int i = 8; i < 16; i++) {
            ull hh = packff(hp[lane + 32 * i]);
            ffma2(aR, wt[0][i], hh); ffma2(aZ, wt[1][i], hh); ffma2(aN, wt[2][i], hh);
        }

#pragma unroll
        for (int o = 16; o; o >>= 1) {
            ull tR = __shfl_xor_sync(0xffffffffu, aR, o);
            ull tZ = __shfl_xor_sync(0xffffffffu, aZ, o);
            ull tN = __shfl_xor_sync(0xffffffffu, aN, o);
            addx2(aR, tR); addx2(aZ, tZ); addx2(aN, tN);
        }
        float2 fR = unpk(aR), fZ = unpk(aZ), fN = unpk(aN);
        float hnew = 0.f;
        if (lane < 2) {
            float aRs = lane ? fR.y : fR.x;
            float aZs = lane ? fZ.y : fZ.x;
            float aNs = lane ? fN.y : fN.x;
            float rr = sigm_(giR + aRs + bR);
            float zz = sigm_(giZ + aZs + bZ);
            float nn = tanh_(giN + rr * (aNs + bN));
            float hprev = hp[myj];
            hnew = (1.f - zz) * nn + zz * hprev;
        }
        float he = __shfl_sync(0xffffffffu, hnew, 0);
        float ho = __shfl_sync(0xffffffffu, hnew, 1);
        if (s + 1 < LL && lane < 16) {
            ull pairv = pack2(he, ho);
            const int nsl = (s + 1) & 1;
            unsigned ldata = (nsl ? sb1 : sb0) + (unsigned)j0 * 4u;
            unsigned lmbar = (rank < 8) ? (nsl ? mA1 : mA0) : (nsl ? mB1 : mB0);
            unsigned rdata, rmbar;
            asm("mapa.shared::cluster.u32 %0, %1, %2;" : "=r"(rdata) : "r"(ldata), "r"(lane));
            asm("mapa.shared::cluster.u32 %0, %1, %2;" : "=r"(rmbar) : "r"(lmbar), "r"(lane));
            asm volatile("st.async.shared::cluster.mbarrier::complete_tx::bytes.b64 [%0], %1, [%2];"
                         :: "r"(rdata), "l"(pairv), "r"(rmbar) : "memory");
        }
        if (lane == 0) *(float2*)&outp[(size_t)t * (2 * HH) + j0] = make_float2(he, ho);
        giR = nxR; giZ = nxZ; giN = nxN;
    }
    asm volatile("barrier.cluster.arrive.aligned;" ::: "memory");
    asm volatile("barrier.cluster.wait.aligned;" ::: "memory");
}

// ---------------- fallback GRU (R3, global-flag sync) ----------------
__global__ void __launch_bounds__(512, 1) gru_flags(
    const float* __restrict__ whh_f, const float* __restrict__ bhh_f,
    const float* __restrict__ whh_b, const float* __restrict__ bhh_b,
    float* __restrict__ out)
{
    const int dir = blockIdx.x >> 5, cta = blockIdx.x & 31;
    const int wrp = threadIdx.x >> 5, lane = threadIdx.x & 31;
    const int j = cta * 16 + wrp;
    const float* whh = dir ? whh_b : whh_f;
    const float* bhh = dir ? bhh_b : bhh_f;
    const float* gi  = dir ? g_gi_b : g_gi_f;

    float wr[16], wz[16], wn[16];
#pragma unroll
    for (int i = 0; i < 16; i++) {
        int k = lane + 32 * i;
        wr[i] = whh[(size_t)j * HH + k];
        wz[i] = whh[(size_t)(HH + j) * HH + k];
        wn[i] = whh[(size_t)(2 * HH + j) * HH + k];
    }
    const float bhr = bhh[j], bhz = bhh[HH + j], bhn = bhh[2 * HH + j];

    for (int s = 0; s < LL; s++) {
        const int t = dir ? (LL - 1 - s) : s;
        float giR = 0.f, giZ = 0.f, giN = 0.f;
        if (lane == 0) {
            const float* gt = gi + (size_t)t * (3 * HH);
            giR = __ldg(&gt[j]); giZ = __ldg(&gt[HH + j]); giN = __ldg(&gt[2 * HH + j]);
        }
        if (s > 0 && wrp == 0) {
            const unsigned tgt = (unsigned)s;
            while (__any_sync(0xffffffffu, ld_acq(&g_flag[dir][lane][0]) < tgt)) {}
        }
        __syncthreads();
        const float* hp = g_h[dir][s & 1];
        float* hn = g_h[dir][(s + 1) & 1];
        float aR = 0.f, aZ = 0.f, aN = 0.f;
#pragma unroll
        for (int i = 0; i < 16; i++) {
            float hv = __ldcg(&hp[lane + 32 * i]);
            aR = fmaf(wr[i], hv, aR);
            aZ = fmaf(wz[i], hv, aZ);
            aN = fmaf(wn[i], hv, aN);
        }
#pragma unroll
        for (int o = 16; o; o >>= 1) {
            aR += __shfl_xor_sync(0xffffffffu, aR, o);
            aZ += __shfl_xor_sync(0xffffffffu, aZ, o);
            aN += __shfl_xor_sync(0xffffffffu, aN, o);
        }
        if (lane == 0) {
            float r = sigm_(giR + aR + bhr);
            float z = sigm_(giZ + aZ + bhz);
            float n = tanh_(giN + r * (aN + bhn));
            float hprev = __ldcg(&hp[j]);
            float hnew = (1.f - z) * n + z * hprev;
            __stcg(&hn[j], hnew);
            out[(size_t)t * (2 * HH) + dir * HH + j] = hnew;
        }
        __syncthreads();
        if (threadIdx.x == 0) st_rel(&g_flag[dir][cta][0], (unsigned)(s + 1));
    }
}

// ---------------- launch ----------------
extern "C" void kernel_launch(void* const* d_in, const int* in_sizes, int n_in,
                              void* d_out, int out_size) {
    const float* v     = (const float*)d_in[0];
    const float* w1    = (const float*)d_in[1];
    const float* b1    = (const float*)d_in[2];
    const float* w2    = (const float*)d_in[3];
    const float* b2    = (const float*)d_in[4];
    const float* wih_f = (const float*)d_in[5];
    const float* whh_f = (const float*)d_in[6];
    const float* bih_f = (const float*)d_in[7];
    const float* bhh_f = (const float*)d_in[8];
    const float* wih_b = (const float*)d_in[9];
    const float* whh_b = (const float*)d_in[10];
    const float* bih_b = (const float*)d_in[11];
    const float* bhh_b = (const float*)d_in[12];
    float* out = (float*)d_out;

    // query cluster feasibility FIRST so launch count is fixed per path
    cudaFuncSetAttribute((const void*)gru_cluster,
                         cudaFuncAttributeNonPortableClusterSizeAllowed, 1);
    cudaLaunchConfig_t cfg = {};
    cfg.gridDim = dim3(32, 1, 1);
    cfg.blockDim = dim3(512, 1, 1);
    cfg.dynamicSmemBytes = 0;
    cfg.stream = 0;
    cudaLaunchAttribute attrs[1];
    attrs[0].id = cudaLaunchAttributeClusterDimension;
    attrs[0].val.clusterDim = {16, 1, 1};
    cfg.attrs = attrs;
    cfg.numAttrs = 1;
    int nclus = 0;
    cudaError_t qe = cudaOccupancyMaxActiveClusters(&nclus, gru_cluster, &cfg);
    bool use_cluster = (qe == cudaSuccess && nclus >= 2);
    if (!use_cluster) cudaGetLastError();

    if (!use_cluster) init_zero<<<2, 1024>>>();           // fallback state only
    gemm_head<<<dim3(24, 8, 4), 256>>>(v, w1, b1, w2, b2,
                                       wih_f, bih_f, wih_b, bih_b);  // idx 0 (cluster path)
    attn_e<<<dim3(16, 32), dim3(32, 16)>>>(v);            // idx 1
    softmax_rows<<<512, 512>>>();                          // idx 2
    gemm_c<<<dim3(8, 8), 256>>>(v);                        // idx 3
    gemm_tail<<<dim3(24, 8, 2), 256>>>(wih_f, wih_b);      // idx 4

    if (use_cluster) {
        cudaError_t le = cudaLaunchKernelEx(&cfg, gru_cluster,
                                            whh_f, bhh_f, whh_b, bhh_b, out);  // idx 5 -> profiled
        if (le != cudaSuccess) {
            cudaGetLastError();
            init_zero<<<2, 1024>>>();
            gru_flags<<<64, 512>>>(whh_f, bhh_f, whh_b, bhh_b, out);
        }
    } else {
        gru_flags<<<64, 512>>>(whh_f, bhh_f, whh_b, bhh_b, out);
    }
}

// round 13
// speedup vs baseline: 4.1578x; 1.0209x over previous
#include <cuda_runtime.h>
#include <cuda_bf16.h>

#define LL 512
#define DD 512
#define HH 512

typedef unsigned long long ull;

// ---------------- device scratch ----------------
__device__ float g_u[LL * DD];
__device__ float g_w[LL * DD];
__device__ float g_e[LL * LL];
__device__ float g_a[LL * LL];
__device__ float g_c[LL * DD];
__device__ float g_gi_f[LL * 3 * HH];
__device__ float g_gi_b[LL * 3 * HH];
__device__ float g_h[2][2][HH];               // fallback: [dir][parity][h]
__device__ unsigned int g_flag[2][32][32];    // fallback: per-producer flag lines

__device__ __forceinline__ float sigm_(float x) {
    return __fdividef(1.f, 1.f + __expf(-x));
}
__device__ __forceinline__ float tanh_(float x) {
    return 1.f - __fdividef(2.f, __expf(x + x) + 1.f);
}
__device__ __forceinline__ unsigned int ld_acq(const unsigned int* p) {
    unsigned int v;
    asm volatile("ld.acquire.gpu.global.u32 %0, [%1];" : "=r"(v) : "l"(p) : "memory");
    return v;
}
__device__ __forceinline__ void st_rel(unsigned int* p, unsigned int v) {
    asm volatile("st.release.gpu.global.u32 [%0], %1;" :: "l"(p), "r"(v) : "memory");
}
__device__ __forceinline__ void ffma2(ull& d, ull a, ull b) {
    asm("fma.rn.f32x2 %0, %1, %2, %0;" : "+l"(d) : "l"(a), "l"(b));
}
__device__ __forceinline__ void addx2(ull& d, ull a) {
    asm("add.rn.f32x2 %0, %0, %1;" : "+l"(d) : "l"(a));
}
__device__ __forceinline__ ull packff(float x) {
    ull r; asm("mov.b64 %0, {%1, %1};" : "=l"(r) : "f"(x)); return r;
}
__device__ __forceinline__ ull pack2(float x, float y) {
    ull r; asm("mov.b64 %0, {%1, %2};" : "=l"(r) : "f"(x), "f"(y)); return r;
}
__device__ __forceinline__ float2 unpk(ull v) {
    float2 f; asm("mov.b64 {%0, %1}, %2;" : "=f"(f.x), "=f"(f.y) : "l"(v)); return f;
}
__device__ __forceinline__ unsigned smem_u32(const void* p) {
    unsigned a;
    asm("{ .reg .u64 t; cvta.to.shared.u64 t, %1; cvt.u32.u64 %0, t; }" : "=r"(a) : "l"(p));
    return a;
}
__device__ __forceinline__ unsigned ctarank_() {
    unsigned r; asm("mov.u32 %0, %%cluster_ctarank;" : "=r"(r)); return r;
}
__device__ __forceinline__ void mbar_wait(unsigned addr, unsigned parity) {
    asm volatile(
        "{\n\t"
        ".reg .pred P;\n\t"
        "WL_%=:\n\t"
        "mbarrier.try_wait.parity.acquire.cta.shared::cta.b64 P, [%0], %1, 0x989680;\n\t"
        "@!P bra WL_%=;\n\t"
        "}"
        :: "r"(addr), "r"(parity) : "memory");
}
__device__ __forceinline__ void mbar_rearm(unsigned addr, unsigned bytes) {
    asm volatile("mbarrier.arrive.expect_tx.shared.b64 _, [%0], %1;"
                 :: "r"(addr), "r"(bytes) : "memory");
}

// ---------------- init (fallback path only) ----------------
__global__ void init_zero() {
    int i = blockIdx.x * 1024 + threadIdx.x;
    if (i < 2048) ((unsigned int*)g_flag)[i] = 0u;
    if (i < 2048) ((float*)g_h)[i] = 0.f;
}

// ---------------- GEMM core (f32x2 packed, lda/ldb/accum generalized) ----------------
__device__ __forceinline__ void gemm_core(
    const float* __restrict__ A, int lda,
    const float* __restrict__ B, int ldb,
    const float* __restrict__ bias, float* __restrict__ C,
    int N, int Kloop, int transB, int accum)
{
    __shared__ __align__(16) float As[16][68];
    __shared__ __align__(16) float Bs[16][68];
    const int tid = threadIdx.x;
    const int m0 = blockIdx.y * 64, n0 = blockIdx.x * 64;
    const int tm = (tid >> 4) * 4, tn = (tid & 15) * 4;
    ull acc[4][2] = {};
    for (int k0 = 0; k0 < Kloop; k0 += 16) {
#pragma unroll
        for (int i = 0; i < 4; i++) {
            int e = tid + 256 * i;
            {
                int kk = e & 15, row = e >> 4;
                As[kk][row] = A[(size_t)(m0 + row) * lda + k0 + kk];
            }
            if (transB) {
                int kk = e & 15, row = e >> 4;
                Bs[kk][row] = B[(size_t)(n0 + row) * ldb + k0 + kk];
            } else {
                int n = e & 63, kk = e >> 6;
                Bs[kk][n] = B[(size_t)(k0 + kk) * ldb + n0 + n];
            }
        }
        __syncthreads();
#pragma unroll
        for (int kk = 0; kk < 16; kk++) {
            float4 a = *(const float4*)&As[kk][tm];
            const ull* bp = (const ull*)&Bs[kk][tn];
            ull b01 = bp[0], b23 = bp[1];
            ull a0 = packff(a.x), a1 = packff(a.y), a2 = packff(a.z), a3 = packff(a.w);
            ffma2(acc[0][0], a0, b01); ffma2(acc[0][1], a0, b23);
            ffma2(acc[1][0], a1, b01); ffma2(acc[1][1], a1, b23);
            ffma2(acc[2][0], a2, b01); ffma2(acc[2][1], a2, b23);
            ffma2(acc[3][0], a3, b01); ffma2(acc[3][1], a3, b23);
        }
        __syncthreads();
    }
#pragma unroll
    for (int i = 0; i < 4; i++) {
        float2 c01 = unpk(acc[i][0]), c23 = unpk(acc[i][1]);
        float* cp = C + (size_t)(m0 + tm + i) * N + n0 + tn;
        float b0 = 0.f, b1 = 0.f, b2 = 0.f, b3 = 0.f;
        if (bias) { b0 = bias[n0+tn]; b1 = bias[n0+tn+1]; b2 = bias[n0+tn+2]; b3 = bias[n0+tn+3]; }
        if (accum) { b0 += cp[0]; b1 += cp[1]; b2 += cp[2]; b3 += cp[3]; }
        cp[0] = c01.x + b0; cp[1] = c01.y + b1; cp[2] = c23.x + b2; cp[3] = c23.y + b3;
    }
}

// head: z=0 -> u, z=1 -> w (8x8 blocks), z=2 -> gi_f v-half, z=3 -> gi_b v-half (24x8)
__global__ void gemm_head(const float* __restrict__ v,
                          const float* __restrict__ w1, const float* __restrict__ b1,
                          const float* __restrict__ w2, const float* __restrict__ b2,
                          const float* __restrict__ wih_f, const float* __restrict__ bih_f,
                          const float* __restrict__ wih_b, const float* __restrict__ bih_b) {
    const int z = blockIdx.z;
    if (z < 2) {
        if (blockIdx.x >= 8) return;
        if (z == 0) gemm_core(v, 512, w1, 512, b1, g_u, 512, 512, 1, 0);
        else        gemm_core(v, 512, w2, 512, b2, g_w, 512, 512, 1, 0);
    } else {
        if (z == 2) gemm_core(v, 512, wih_f, 1024, bih_f, g_gi_f, 1536, 512, 1, 0);
        else        gemm_core(v, 512, wih_b, 1024, bih_b, g_gi_b, 1536, 512, 1, 0);
    }
}
// c = a @ v with 32x64 tiles (128 CTAs, better occupancy for the small GEMM)
__global__ void gemm_c32(const float* __restrict__ v) {
    __shared__ __align__(16) float As[16][36];
    __shared__ __align__(16) float Bs[16][68];
    const int tid = threadIdx.x;
    const int m0 = blockIdx.y * 32, n0 = blockIdx.x * 64;
    const int tm = (tid >> 4) * 2, tn = (tid & 15) * 4;
    ull acc[2][2] = {};
    for (int k0 = 0; k0 < 512; k0 += 16) {
#pragma unroll
        for (int i = 0; i < 2; i++) {
            int e = tid + 256 * i;
            int kk = e & 15, row = e >> 4;
            As[kk][row] = g_a[(size_t)(m0 + row) * 512 + k0 + kk];
        }
#pragma unroll
        for (int i = 0; i < 4; i++) {
            int e = tid + 256 * i;
            int n = e & 63, kk = e >> 6;
            Bs[kk][n] = v[(size_t)(k0 + kk) * 512 + n0 + n];
        }
        __syncthreads();
#pragma unroll
        for (int kk = 0; kk < 16; kk++) {
            float2 a2 = *(const float2*)&As[kk][tm];
            const ull* bp = (const ull*)&Bs[kk][tn];
            ull b01 = bp[0], b23 = bp[1];
            ull a0 = packff(a2.x), a1 = packff(a2.y);
            ffma2(acc[0][0], a0, b01); ffma2(acc[0][1], a0, b23);
            ffma2(acc[1][0], a1, b01); ffma2(acc[1][1], a1, b23);
        }
        __syncthreads();
    }
#pragma unroll
    for (int i = 0; i < 2; i++) {
        float2 c01 = unpk(acc[i][0]), c23 = unpk(acc[i][1]);
        float* cp = g_c + (size_t)(m0 + tm + i) * 512 + n0 + tn;
        cp[0] = c01.x; cp[1] = c01.y; cp[2] = c23.x; cp[3] = c23.y;
    }
}
__global__ void gemm_tail(const float* __restrict__ wih_f, const float* __restrict__ wih_b) {
    if (blockIdx.z == 0) gemm_core(g_c, 512, wih_f + 512, 1024, nullptr, g_gi_f, 1536, 512, 1, 1);
    else                 gemm_core(g_c, 512, wih_b + 512, 1024, nullptr, g_gi_b, 1536, 512, 1, 1);
}

// ---------------- attn e ----------------
__global__ void attn_e(const float* __restrict__ v) {
    __shared__ float us[32][33], vs[32][33], ws[16][33];
    const int tx = threadIdx.x, ty = threadIdx.y;
    const int j0 = blockIdx.x * 32, t0 = blockIdx.y * 16;
    float acc = 0.f;
    for (int d0 = 0; d0 < DD; d0 += 32) {
        us[ty][tx]      = g_u[(j0 + ty) * DD + d0 + tx];
        us[ty + 16][tx] = g_u[(j0 + ty + 16) * DD + d0 + tx];
        vs[ty][tx]      = v[(j0 + ty) * DD + d0 + tx];
        vs[ty + 16][tx] = v[(j0 + ty + 16) * DD + d0 + tx];
        ws[ty][tx]      = g_w[(t0 + ty) * DD + d0 + tx];
        __syncthreads();
#pragma unroll
        for (int dd = 0; dd < 32; dd++) {
            float x = us[tx][dd] + ws[ty][dd];
            float th = 1.f - __fdividef(2.f, __expf(x + x) + 1.f);
            acc = fmaf(th, vs[tx][dd], acc);
        }
        __syncthreads();
    }
    g_e[(t0 + ty) * LL + j0 + tx] = acc;
}

// ---------------- softmax rows ----------------
__global__ void softmax_rows() {
    __shared__ float red[16];
    __shared__ float bval;
    const int t = blockIdx.x, tid = threadIdx.x, w = tid >> 5, l = tid & 31;
    float x = g_e[t * LL + tid];
    float m = x;
#pragma unroll
    for (int o = 16; o; o >>= 1) m = fmaxf(m, __shfl_xor_sync(~0u, m, o));
    if (l == 0) red[w] = m;
    __syncthreads();
    if (tid == 0) {
        float mm = red[0];
#pragma unroll
        for (int i = 1; i < 16; i++) mm = fmaxf(mm, red[i]);
        bval = mm;
    }
    __syncthreads();
    float p = __expf(x - bval);
    float s = p;
#pragma unroll
    for (int o = 16; o; o >>= 1) s += __shfl_xor_sync(~0u, s, o);
    if (l == 0) red[w] = s;
    __syncthreads();
    if (tid == 0) {
        float ss = red[0];
#pragma unroll
        for (int i = 1; i < 16; i++) ss += red[i];
        bval = ss;
    }
    __syncthreads();
    g_a[t * LL + tid] = __fdividef(p, bval);
}

// ======== GRU scan: 16-CTA cluster, 4-chunk st.async publish + half-warp gates ========
// h layout: thread covers k = lane + 32*i; chunk c = source ranks 4c..4c+3
// (iterations i = 4c..4c+3), per-chunk mbarrier expect_tx = 512B.
// Gates: lanes 0-15 compute h_even, lanes 16-31 h_odd; partner via shfl_xor 16.
__global__ void __launch_bounds__(512, 1) gru_cluster(
    const float* __restrict__ whh_f, const float* __restrict__ bhh_f,
    const float* __restrict__ whh_b, const float* __restrict__ bhh_b,
    float* __restrict__ out)
{
    __shared__ __align__(16) float hbuf[2][HH];
    __shared__ __align__(8) ull mbC[4][2];
    const int dir = blockIdx.x >> 4;
    const int wrp = threadIdx.x >> 5, lane = threadIdx.x & 31;
    const unsigned rank = ctarank_();
    const int j0 = (int)rank * 32 + wrp * 2;
    const int half = lane >> 4;          // 0 -> h_even (j0), 1 -> h_odd (j0+1)
    const int jh = j0 + half;
    const float* whh = dir ? whh_b : whh_f;
    const float* bhh = dir ? bhh_b : bhh_f;
    const float* gi  = dir ? g_gi_b : g_gi_f;
    float* outp = out + dir * HH;

    // weights packed for k = lane + 32*i, pair = (row j0, row j0+1)
    ull wt[3][16];
#pragma unroll
    for (int g = 0; g < 3; g++) {
        const float* r0 = whh + ((size_t)(g * HH + j0)) * HH;
        const float* r1 = r0 + HH;
#pragma unroll
        for (int i = 0; i < 16; i++) {
            int k = lane + 32 * i;
            wt[g][i] = pack2(r0[k], r1[k]);
        }
    }
    const float bRs = bhh[jh], bZs = bhh[HH + jh], bNs = bhh[2 * HH + jh];

    for (int i = threadIdx.x; i < HH; i += 512) hbuf[0][i] = 0.f;
    const unsigned sb0 = smem_u32(&hbuf[0][0]);
    const unsigned sb1 = smem_u32(&hbuf[1][0]);
    const unsigned mbc = smem_u32(&mbC[0][0]);
    if (threadIdx.x == 0) {
#pragma unroll
        for (int q = 0; q < 8; q++) {
            asm volatile("mbarrier.init.shared.b64 [%0], %1;"
                         :: "r"(mbc + q * 8u), "r"(1u) : "memory");
            mbar_rearm(mbc + q * 8u, 512u);
        }
    }
    __syncthreads();
    asm volatile("barrier.cluster.arrive.aligned;" ::: "memory");
    asm volatile("barrier.cluster.wait.aligned;" ::: "memory");

    // gi prefetch for step 0 (each lane loads its half's values)
    float giR, giZ, giN;
    {
        const int t0 = dir ? (LL - 1) : 0;
        const float* gt = gi + (size_t)t0 * (3 * HH);
        giR = __ldg(gt + jh); giZ = __ldg(gt + HH + jh); giN = __ldg(gt + 2 * HH + jh);
    }

    unsigned parbits = 0u;   // bit (c*2+sl)
    for (int s = 0; s < LL; s++) {
        const int t = dir ? (LL - 1 - s) : s;
        // prefetch gi for step s+1
        float nxR = 0.f, nxZ = 0.f, nxN = 0.f;
        if (s + 1 < LL) {
            const int tn_ = dir ? (LL - 2 - s) : (s + 1);
            const float* gt = gi + (size_t)tn_ * (3 * HH);
            nxR = __ldg(gt + jh); nxZ = __ldg(gt + HH + jh); nxN = __ldg(gt + 2 * HH + jh);
        }
        const int sl = s & 1;
        const float* hp = hbuf[sl];
        ull aR = 0, aZ = 0, aN = 0;
#pragma unroll
        for (int c = 0; c < 4; c++) {
            if (s > 0) {
                const unsigned idx = (unsigned)(c * 2 + sl);
                const unsigned ma = mbc + idx * 8u;
                mbar_wait(ma, (parbits >> idx) & 1u);
                parbits ^= (1u << idx);
                if (threadIdx.x == 0) mbar_rearm(ma, 512u);
            }
#pragma unroll
            for (int i = 4 * c; i < 4 * c + 4; i++) {
                ull hh = packff(hp[lane + 32 * i]);
                ffma2(aR, wt[0][i], hh); ffma2(aZ, wt[1][i], hh); ffma2(aN, wt[2][i], hh);
            }
        }
#pragma unroll
        for (int o = 16; o; o >>= 1) {
            ull tR = __shfl_xor_sync(0xffffffffu, aR, o);
            ull tZ = __shfl_xor_sync(0xffffffffu, aZ, o);
            ull tN = __shfl_xor_sync(0xffffffffu, aN, o);
            addx2(aR, tR); addx2(aZ, tZ); addx2(aN, tN);
        }
        float2 fR = unpk(aR), fZ = unpk(aZ), fN = unpk(aN);
        // half-warp gates: low lanes h_even, high lanes h_odd
        float aRs = half ? fR.y : fR.x;
        float aZs = half ? fZ.y : fZ.x;
        float aNs = half ? fN.y : fN.x;
        float rr = sigm_(giR + aRs + bRs);
        float zz = sigm_(giZ + aZs + bZs);
        float nn = tanh_(giN + rr * (aNs + bNs));
        float hprev = hp[jh];
        float hv = (1.f - zz) * nn + zz * hprev;
        float hov = __shfl_xor_sync(0xffffffffu, hv, 16);   // partner half's value
        if (s + 1 < LL && lane < 16) {
            ull pairv = pack2(hv, hov);                      // (h_even, h_odd)
            const int nsl = (s + 1) & 1;
            unsigned ldata = (nsl ? sb1 : sb0) + (unsigned)j0 * 4u;
            unsigned lmbar = mbc + (unsigned)((rank >> 2) * 2 + nsl) * 8u;
            unsigned rdata, rmbar;
            asm("mapa.shared::cluster.u32 %0, %1, %2;" : "=r"(rdata) : "r"(ldata), "r"(lane));
            asm("mapa.shared::cluster.u32 %0, %1, %2;" : "=r"(rmbar) : "r"(lmbar), "r"(lane));
            asm volatile("st.async.shared::cluster.mbarrier::complete_tx::bytes.b64 [%0], %1, [%2];"
                         :: "r"(rdata), "l"(pairv), "r"(rmbar) : "memory");
        }
        if (lane == 0) *(float2*)&outp[(size_t)t * (2 * HH) + j0] = make_float2(hv, hov);
        giR = nxR; giZ = nxZ; giN = nxN;
    }
    asm volatile("barrier.cluster.arrive.aligned;" ::: "memory");
    asm volatile("barrier.cluster.wait.aligned;" ::: "memory");
}

// ---------------- fallback GRU (R3, global-flag sync) ----------------
__global__ void __launch_bounds__(512, 1) gru_flags(
    const float* __restrict__ whh_f, const float* __restrict__ bhh_f,
    const float* __restrict__ whh_b, const float* __restrict__ bhh_b,
    float* __restrict__ out)
{
    const int dir = blockIdx.x >> 5, cta = blockIdx.x & 31;
    const int wrp = threadIdx.x >> 5, lane = threadIdx.x & 31;
    const int j = cta * 16 + wrp;
    const float* whh = dir ? whh_b : whh_f;
    const float* bhh = dir ? bhh_b : bhh_f;
    const float* gi  = dir ? g_gi_b : g_gi_f;

    float wr[16], wz[16], wn[16];
#pragma unroll
    for (int i = 0; i < 16; i++) {
        int k = lane + 32 * i;
        wr[i] = whh[(size_t)j * HH + k];
        wz[i] = whh[(size_t)(HH + j) * HH + k];
        wn[i] = whh[(size_t)(2 * HH + j) * HH + k];
    }
    const float bhr = bhh[j], bhz = bhh[HH + j], bhn = bhh[2 * HH + j];

    for (int s = 0; s < LL; s++) {
        const int t = dir ? (LL - 1 - s) : s;
        float giR = 0.f, giZ = 0.f, giN = 0.f;
        if (lane == 0) {
            const float* gt = gi + (size_t)t * (3 * HH);
            giR = __ldg(&gt[j]); giZ = __ldg(&gt[HH + j]); giN = __ldg(&gt[2 * HH + j]);
        }
        if (s > 0 && wrp == 0) {
            const unsigned tgt = (unsigned)s;
            while (__any_sync(0xffffffffu, ld_acq(&g_flag[dir][lane][0]) < tgt)) {}
        }
        __syncthreads();
        const float* hp = g_h[dir][s & 1];
        float* hn = g_h[dir][(s + 1) & 1];
        float aR = 0.f, aZ = 0.f, aN = 0.f;
#pragma unroll
        for (int i = 0; i < 16; i++) {
            float hv = __ldcg(&hp[lane + 32 * i]);
            aR = fmaf(wr[i], hv, aR);
            aZ = fmaf(wz[i], hv, aZ);
            aN = fmaf(wn[i], hv, aN);
        }
#pragma unroll
        for (int o = 16; o; o >>= 1) {
            aR += __shfl_xor_sync(0xffffffffu, aR, o);
            aZ += __shfl_xor_sync(0xffffffffu, aZ, o);
            aN += __shfl_xor_sync(0xffffffffu, aN, o);
        }
        if (lane == 0) {
            float r = sigm_(giR + aR + bhr);
            float z = sigm_(giZ + aZ + bhz);
            float n = tanh_(giN + r * (aN + bhn));
            float hprev = __ldcg(&hp[j]);
            float hnew = (1.f - z) * n + z * hprev;
            __stcg(&hn[j], hnew);
            out[(size_t)t * (2 * HH) + dir * HH + j] = hnew;
        }
        __syncthreads();
        if (threadIdx.x == 0) st_rel(&g_flag[dir][cta][0], (unsigned)(s + 1));
    }
}

// ---------------- launch ----------------
extern "C" void kernel_launch(void* const* d_in, const int* in_sizes, int n_in,
                              void* d_out, int out_size) {
    const float* v     = (const float*)d_in[0];
    const float* w1    = (const float*)d_in[1];
    const float* b1    = (const float*)d_in[2];
    const float* w2    = (const float*)d_in[3];
    const float* b2    = (const float*)d_in[4];
    const float* wih_f = (const float*)d_in[5];
    const float* whh_f = (const float*)d_in[6];
    const float* bih_f = (const float*)d_in[7];
    const float* bhh_f = (const float*)d_in[8];
    const float* wih_b = (const float*)d_in[9];
    const float* whh_b = (const float*)d_in[10];
    const float* bih_b = (const float*)d_in[11];
    const float* bhh_b = (const float*)d_in[12];
    float* out = (float*)d_out;

    cudaFuncSetAttribute((const void*)gru_cluster,
                         cudaFuncAttributeNonPortableClusterSizeAllowed, 1);
    cudaLaunchConfig_t cfg = {};
    cfg.gridDim = dim3(32, 1, 1);
    cfg.blockDim = dim3(512, 1, 1);
    cfg.dynamicSmemBytes = 0;
    cfg.stream = 0;
    cudaLaunchAttribute attrs[1];
    attrs[0].id = cudaLaunchAttributeClusterDimension;
    attrs[0].val.clusterDim = {16, 1, 1};
    cfg.attrs = attrs;
    cfg.numAttrs = 1;
    int nclus = 0;
    cudaError_t qe = cudaOccupancyMaxActiveClusters(&nclus, gru_cluster, &cfg);
    bool use_cluster = (qe == cudaSuccess && nclus >= 2);
    if (!use_cluster) cudaGetLastError();

    if (!use_cluster) init_zero<<<2, 1024>>>();
    gemm_head<<<dim3(24, 8, 4), 256>>>(v, w1, b1, w2, b2,
                                       wih_f, bih_f, wih_b, bih_b);  // idx 0
    attn_e<<<dim3(16, 32), dim3(32, 16)>>>(v);                        // idx 1
    softmax_rows<<<512, 512>>>();                                     // idx 2
    gemm_c32<<<dim3(8, 16), 256>>>(v);                                // idx 3
    gemm_tail<<<dim3(24, 8, 2), 256>>>(wih_f, wih_b);                 // idx 4

    if (use_cluster) {
        cudaError_t le = cudaLaunchKernelEx(&cfg, gru_cluster,
                                            whh_f, bhh_f, whh_b, bhh_b, out);  // idx 5
        if (le != cudaSuccess) {
            cudaGetLastError();
            init_zero<<<2, 1024>>>();
            gru_flags<<<64, 512>>>(whh_f, bhh_f, whh_b, bhh_b, out);
        }
    } else {
        gru_flags<<<64, 512>>>(whh_f, bhh_f, whh_b, bhh_b, out);
    }
}